// round 12
// baseline (speedup 1.0000x reference)
#include <cuda_runtime.h>
#include <cuda_bf16.h>

// ---------------- Problem constants ----------------
#define Bn    64
#define Tn    256
#define Cn    256
#define Hn    8
#define HSn   32         // head size
#define Ln    6
#define Vn    96
#define NROWS (Bn*Tn)    // 16384
#define CC    (Cn*Cn)    // 65536
#define EPSF  1e-5f
#define KK    256        // K dim of every GEMM

// ---------------- Scratch (static device memory; no allocation) ----------------
__device__ float g_scratch[5 * NROWS * Cn + NROWS];

// ---------------- Embedding ----------------
__global__ void embed_kernel(const int* __restrict__ idx,
                             const float* __restrict__ tok,
                             const float* __restrict__ pos,
                             float* __restrict__ x) {
    int row = blockIdx.x;
    int c = threadIdx.x;
    int token = idx[row];
    x[row * Cn + c] = tok[token * Cn + c] + pos[(row & (Tn - 1)) * Cn + c];
}

// ---------------- tf32 helpers ----------------
__device__ __forceinline__ unsigned f2tf(float f) {
    unsigned u;
    asm("cvt.rna.tf32.f32 %0, %1;" : "=r"(u) : "f"(f));
    return u;
}

__device__ __forceinline__ void mma_tf32(float* d, const unsigned* a, const unsigned* b) {
    asm volatile("mma.sync.aligned.m16n8k8.row.col.f32.tf32.tf32.f32 "
        "{%0,%1,%2,%3}, {%4,%5,%6,%7}, {%8,%9}, {%0,%1,%2,%3};"
        : "+f"(d[0]), "+f"(d[1]), "+f"(d[2]), "+f"(d[3])
        : "r"(a[0]), "r"(a[1]), "r"(a[2]), "r"(a[3]), "r"(b[0]), "r"(b[1]));
}

// ---------------- Tensor-core tf32 GEMM (fragment-ordered smem) ----------------
// Cout[M,Nd] = A[M,256] @ W[256,Nd] (+bias)(+relu). CTA 128x64, BK=32,
// 8 warps (4M x 2N), warp tile 32x32.
// Shared memory holds each mma tile in FRAGMENT order:
//   A tile (m16k8), tile idx = mt*4+ks, elem = lane*4 + reg (reg=half*2+i2)
//   B tile (k8n8),  tile idx = ks*8+nt, elem = (g*4+t)*2 + half
// so fragment loads are 2xLDS.128 + 4xLDS.64 per kstep, conflict-free.
#define APAD 132
#define BPAD 66
#define A_BUF (32*APAD)   // 4224 u32 (8 mt x 4 ks tiles)
#define B_BUF (32*BPAD)   // 2112 u32 (4 ks x 8 nt tiles)
#define GSMEM ((2*A_BUF + 2*B_BUF) * 4)   // 50688 bytes

__device__ __forceinline__ void gemm_core(
    const float* __restrict__ A, const float* __restrict__ W,
    const float* __restrict__ bias, float* __restrict__ Cout,
    int Nd, int relu, int transT, unsigned* gsm)
{
    const int tid = threadIdx.x;
    const int lane = tid & 31, warp = tid >> 5;
    const int g = lane >> 2, t = lane & 3;
    const int wm = (warp & 3) * 32, wn = (warp >> 2) * 32;
    const int mt0 = (warp & 3) * 2;
    const int nt0 = (warp >> 2) * 4;
    const int aRowBase = blockIdx.y * 128;
    const int bColBase = blockIdx.x * 64;

    float acc[2][4][4] = {};
    float4 ar[4];
    float4 br[2];

    // per-thread constant offsets
    int aGrow[4], aSoff[4];
    const int aGcol0 = (tid & 7) << 2;
    #pragma unroll
    for (int i = 0; i < 4; i++) {
        int fi = tid + i * 256;
        int r = fi >> 3;
        aGrow[i] = r;
        int mt = r >> 4, rr = r & 15;
        int ks = aGcol0 >> 3, half = (aGcol0 >> 2) & 1;
        aSoff[i] = (mt * 4 + ks) * APAD + (rr & 7) * 16 + half * 2 + (rr >> 3);
    }
    int bGrow[2], bSoff[2];
    const int bGcol0 = (tid & 15) << 2;
    #pragma unroll
    for (int i = 0; i < 2; i++) {
        int fi = tid + i * 256;
        int r = fi >> 4;
        bGrow[i] = r;
        int ks = r >> 3, kk = r & 7;
        int nt = bGcol0 >> 3, g0 = bGcol0 & 7;
        bSoff[i] = (ks * 8 + nt) * BPAD + g0 * 8 + (kk & 3) * 2 + (kk >> 2);
    }
    const int wcol = bColBase + bGcol0;

    // prologue: prefetch chunk 0
    #pragma unroll
    for (int i = 0; i < 4; i++)
        ar[i] = *(const float4*)(A + (size_t)(aRowBase + aGrow[i]) * KK + aGcol0);
    #pragma unroll
    for (int i = 0; i < 2; i++)
        br[i] = (wcol < Nd) ? *(const float4*)(W + (size_t)bGrow[i] * Nd + wcol)
                            : make_float4(0.f, 0.f, 0.f, 0.f);
    // store chunk 0 into buffer 0 (fragment order)
    {
        unsigned* Asb = gsm;
        unsigned* Bsb = gsm + 2 * A_BUF;
        #pragma unroll
        for (int i = 0; i < 4; i++) {
            unsigned* p = Asb + aSoff[i];
            p[0]  = f2tf(ar[i].x); p[4]  = f2tf(ar[i].y);
            p[8]  = f2tf(ar[i].z); p[12] = f2tf(ar[i].w);
        }
        #pragma unroll
        for (int i = 0; i < 2; i++) {
            unsigned* p = Bsb + bSoff[i];
            p[0]  = f2tf(br[i].x); p[8]  = f2tf(br[i].y);
            p[16] = f2tf(br[i].z); p[24] = f2tf(br[i].w);
        }
    }
    __syncthreads();

    for (int kt = 0; kt < 8; kt++) {
        int cur = kt & 1;
        const unsigned* As = gsm + cur * A_BUF;
        const unsigned* Bs = gsm + 2 * A_BUF + cur * B_BUF;

        // prefetch next chunk (global) — overlaps compute below
        if (kt < 7) {
            int kn = (kt + 1) * 32;
            #pragma unroll
            for (int i = 0; i < 4; i++)
                ar[i] = *(const float4*)(A + (size_t)(aRowBase + aGrow[i]) * KK + kn + aGcol0);
            #pragma unroll
            for (int i = 0; i < 2; i++)
                br[i] = (wcol < Nd) ? *(const float4*)(W + (size_t)(kn + bGrow[i]) * Nd + wcol)
                                    : make_float4(0.f, 0.f, 0.f, 0.f);
        }

        // compute: 4 ksteps, fragment loads are vectorized & conflict-free
        #pragma unroll
        for (int ks = 0; ks < 4; ks++) {
            uint4 af[2];
            uint2 bf[4];
            af[0] = *(const uint4*)&As[((mt0    ) * 4 + ks) * APAD + lane * 4];
            af[1] = *(const uint4*)&As[((mt0 + 1) * 4 + ks) * APAD + lane * 4];
            #pragma unroll
            for (int j = 0; j < 4; j++)
                bf[j] = *(const uint2*)&Bs[(ks * 8 + nt0 + j) * BPAD + g * 8 + t * 2];
            #pragma unroll
            for (int i = 0; i < 2; i++)
                #pragma unroll
                for (int j = 0; j < 4; j++)
                    mma_tf32(acc[i][j], (const unsigned*)&af[i], (const unsigned*)&bf[j]);
        }

        // store prefetched chunk into the other buffer
        if (kt < 7) {
            unsigned* Asn = gsm + (1 - cur) * A_BUF;
            unsigned* Bsn = gsm + 2 * A_BUF + (1 - cur) * B_BUF;
            #pragma unroll
            for (int i = 0; i < 4; i++) {
                unsigned* p = Asn + aSoff[i];
                p[0]  = f2tf(ar[i].x); p[4]  = f2tf(ar[i].y);
                p[8]  = f2tf(ar[i].z); p[12] = f2tf(ar[i].w);
            }
            #pragma unroll
            for (int i = 0; i < 2; i++) {
                unsigned* p = Bsn + bSoff[i];
                p[0]  = f2tf(br[i].x); p[8]  = f2tf(br[i].y);
                p[16] = f2tf(br[i].z); p[24] = f2tf(br[i].w);
            }
        }
        __syncthreads();
    }

    if (!transT) {
        #pragma unroll
        for (int i = 0; i < 2; i++) {
            #pragma unroll
            for (int j = 0; j < 4; j++) {
                int col = bColBase + wn + j * 8 + t * 2;
                if (col >= Nd) continue;
                float bx = 0.f, by = 0.f;
                if (bias) { bx = bias[col]; by = bias[col + 1]; }
                int r0 = aRowBase + wm + i * 16 + g;
                float v0 = acc[i][j][0] + bx, v1 = acc[i][j][1] + by;
                float v2 = acc[i][j][2] + bx, v3 = acc[i][j][3] + by;
                if (relu) {
                    v0 = fmaxf(v0, 0.f); v1 = fmaxf(v1, 0.f);
                    v2 = fmaxf(v2, 0.f); v3 = fmaxf(v3, 0.f);
                }
                *(float2*)&Cout[(size_t)r0 * Nd + col]       = make_float2(v0, v1);
                *(float2*)&Cout[(size_t)(r0 + 8) * Nd + col] = make_float2(v2, v3);
            }
        }
    } else {
        // transposed epilogue: out[b][c][t], per-warp smem transpose patch
        float* patch = (float*)gsm + warp * 1056;   // 32 cols x 32 rows, stride 33
        #pragma unroll
        for (int i = 0; i < 2; i++) {
            #pragma unroll
            for (int j = 0; j < 4; j++) {
                int c0 = j * 8 + t * 2;
                int r0 = i * 16 + g;
                patch[(c0    ) * 33 + r0    ] = acc[i][j][0];
                patch[(c0 + 1) * 33 + r0    ] = acc[i][j][1];
                patch[(c0    ) * 33 + r0 + 8] = acc[i][j][2];
                patch[(c0 + 1) * 33 + r0 + 8] = acc[i][j][3];
            }
        }
        __syncwarp();
        int rowG = aRowBase + wm;
        int bIdx = rowG >> 8;
        int tg = (lane & 7) * 4;
        int chi = lane >> 3;
        int tBase = (rowG & 255) + tg;
        #pragma unroll
        for (int jj = 0; jj < 8; jj++) {
            int c = jj * 4 + chi;
            float4 v;
            v.x = patch[c * 33 + tg + 0];
            v.y = patch[c * 33 + tg + 1];
            v.z = patch[c * 33 + tg + 2];
            v.w = patch[c * 33 + tg + 3];
            *(float4*)&Cout[(size_t)bIdx * (Cn * Tn) +
                            (size_t)(bColBase + wn + c) * Tn + tBase] = v;
        }
    }
}

__global__ __launch_bounds__(256, 2) void gemm_tc_kernel(
    const float* __restrict__ A, const float* __restrict__ W,
    const float* __restrict__ bias, float* __restrict__ Cout,
    int Nd, int relu, int transT)
{
    extern __shared__ unsigned gsm[];
    gemm_core(A, W, bias, Cout, Nd, relu, transT, gsm);
}

// fused Q/K/V projections: blockIdx.z selects weight/output; K written transposed
__global__ __launch_bounds__(256, 2) void gemm_qkv_kernel(
    const float* __restrict__ A,
    const float* __restrict__ Wq, const float* __restrict__ Wk,
    const float* __restrict__ Wv,
    float* __restrict__ oq, float* __restrict__ okt, float* __restrict__ ov)
{
    extern __shared__ unsigned gsm[];
    int z = blockIdx.z;
    const float* W = (z == 0) ? Wq : (z == 1) ? Wk : Wv;
    float*       o = (z == 0) ? oq : (z == 1) ? okt : ov;
    gemm_core(A, W, nullptr, o, Cn, 0, (z == 1) ? 1 : 0, gsm);
}

// ---------------- Tensor-core flash attention ----------------
#define KSTR 72
#define VSTR 40
#define PSTR 68

__global__ __launch_bounds__(128, 4) void attn_tc_kernel(
    const float* __restrict__ Q,    // [B*T, C]
    const float* __restrict__ KT,   // [B][C][T]
    const float* __restrict__ V,    // [B*T, C]
    float* __restrict__ O)          // [B*T, C]
{
    __shared__ unsigned Ks[32 * KSTR];
    __shared__ unsigned Vs[64 * VSTR];
    __shared__ unsigned Ps[4][16 * PSTR];

    int qb = 3 - blockIdx.x;          // heavy blocks first
    int h  = blockIdx.y;
    int b  = blockIdx.z;
    int tid = threadIdx.x;
    int warp = tid >> 5, lane = tid & 31;
    int g = lane >> 2, t = lane & 3;
    int hsoff = h * HSn;
    int q0 = qb * 64;
    int qrow = q0 + warp * 16;

    unsigned qa[4][4];
    {
        const float* Qb = Q + (size_t)(b * Tn + qrow) * Cn + hsoff;
        #pragma unroll
        for (int ks = 0; ks < 4; ks++) {
            qa[ks][0] = f2tf(Qb[(size_t)g       * Cn + ks * 8 + t    ] * 0.0625f);
            qa[ks][1] = f2tf(Qb[(size_t)(g + 8) * Cn + ks * 8 + t    ] * 0.0625f);
            qa[ks][2] = f2tf(Qb[(size_t)g       * Cn + ks * 8 + t + 4] * 0.0625f);
            qa[ks][3] = f2tf(Qb[(size_t)(g + 8) * Cn + ks * 8 + t + 4] * 0.0625f);
        }
    }

    float oa[4][4] = {};
    float m0 = -1e30f, m1 = -1e30f, l0 = 0.f, l1 = 0.f;

    const float* KTb = KT + (size_t)b * (Cn * Tn) + (size_t)hsoff * Tn;
    const float* Vb  = V  + (size_t)(b * Tn) * Cn + hsoff;
    unsigned* Pw = Ps[warp];

    for (int kc = 0; kc <= qb; kc++) {
        __syncthreads();
        #pragma unroll
        for (int i = 0; i < 4; i++) {
            int fi = tid + i * 128;
            int r = fi >> 4, c4 = (fi & 15) << 2;
            float4 v = *(const float4*)(KTb + (size_t)r * Tn + kc * 64 + c4);
            uint4 u = { f2tf(v.x), f2tf(v.y), f2tf(v.z), f2tf(v.w) };
            *(uint4*)&Ks[r * KSTR + c4] = u;
        }
        #pragma unroll
        for (int i = 0; i < 4; i++) {
            int fi = tid + i * 128;
            int r = fi >> 3, c4 = (fi & 7) << 2;
            float4 v = *(const float4*)(Vb + (size_t)(kc * 64 + r) * Cn + c4);
            uint4 u = { f2tf(v.x), f2tf(v.y), f2tf(v.z), f2tf(v.w) };
            *(uint4*)&Vs[r * VSTR + c4] = u;
        }
        __syncthreads();

        float sc[8][4];
        #pragma unroll
        for (int nf = 0; nf < 8; nf++)
            #pragma unroll
            for (int j = 0; j < 4; j++) sc[nf][j] = 0.f;
        #pragma unroll
        for (int ks = 0; ks < 4; ks++) {
            #pragma unroll
            for (int nf = 0; nf < 8; nf++) {
                unsigned bf[2];
                bf[0] = Ks[(ks * 8 + t    ) * KSTR + nf * 8 + g];
                bf[1] = Ks[(ks * 8 + t + 4) * KSTR + nf * 8 + g];
                mma_tf32(sc[nf], qa[ks], bf);
            }
        }

        if (kc == qb) {
            int r0 = warp * 16 + g;
            #pragma unroll
            for (int nf = 0; nf < 8; nf++) {
                int c0 = nf * 8 + 2 * t;
                if (c0     > r0    ) sc[nf][0] = -1e30f;
                if (c0 + 1 > r0    ) sc[nf][1] = -1e30f;
                if (c0     > r0 + 8) sc[nf][2] = -1e30f;
                if (c0 + 1 > r0 + 8) sc[nf][3] = -1e30f;
            }
        }

        float mx0 = -1e30f, mx1 = -1e30f;
        #pragma unroll
        for (int nf = 0; nf < 8; nf++) {
            mx0 = fmaxf(mx0, fmaxf(sc[nf][0], sc[nf][1]));
            mx1 = fmaxf(mx1, fmaxf(sc[nf][2], sc[nf][3]));
        }
        #pragma unroll
        for (int o = 1; o <= 2; o <<= 1) {
            mx0 = fmaxf(mx0, __shfl_xor_sync(0xFFFFFFFFu, mx0, o));
            mx1 = fmaxf(mx1, __shfl_xor_sync(0xFFFFFFFFu, mx1, o));
        }
        float nm0 = fmaxf(m0, mx0), nm1 = fmaxf(m1, mx1);
        float al0 = __expf(m0 - nm0), al1 = __expf(m1 - nm1);

        float s0 = 0.f, s1 = 0.f;
        #pragma unroll
        for (int nf = 0; nf < 8; nf++) {
            float p0 = __expf(sc[nf][0] - nm0);
            float p1 = __expf(sc[nf][1] - nm0);
            float p2 = __expf(sc[nf][2] - nm1);
            float p3 = __expf(sc[nf][3] - nm1);
            s0 += p0 + p1; s1 += p2 + p3;
            uint2 u01 = make_uint2(f2tf(p0), f2tf(p1));
            uint2 u23 = make_uint2(f2tf(p2), f2tf(p3));
            *(uint2*)&Pw[(g    ) * PSTR + nf * 8 + 2 * t] = u01;
            *(uint2*)&Pw[(g + 8) * PSTR + nf * 8 + 2 * t] = u23;
        }
        #pragma unroll
        for (int o = 1; o <= 2; o <<= 1) {
            s0 += __shfl_xor_sync(0xFFFFFFFFu, s0, o);
            s1 += __shfl_xor_sync(0xFFFFFFFFu, s1, o);
        }
        l0 = l0 * al0 + s0;
        l1 = l1 * al1 + s1;
        m0 = nm0; m1 = nm1;

        #pragma unroll
        for (int nf = 0; nf < 4; nf++) {
            oa[nf][0] *= al0; oa[nf][1] *= al0;
            oa[nf][2] *= al1; oa[nf][3] *= al1;
        }
        __syncwarp();

        #pragma unroll
        for (int ks = 0; ks < 8; ks++) {
            unsigned pa[4];
            pa[0] = Pw[(g    ) * PSTR + ks * 8 + t    ];
            pa[1] = Pw[(g + 8) * PSTR + ks * 8 + t    ];
            pa[2] = Pw[(g    ) * PSTR + ks * 8 + t + 4];
            pa[3] = Pw[(g + 8) * PSTR + ks * 8 + t + 4];
            #pragma unroll
            for (int nf = 0; nf < 4; nf++) {
                unsigned vb[2];
                vb[0] = Vs[(ks * 8 + t    ) * VSTR + nf * 8 + g];
                vb[1] = Vs[(ks * 8 + t + 4) * VSTR + nf * 8 + g];
                mma_tf32(oa[nf], pa, vb);
            }
        }
    }

    float i0 = 1.f / l0, i1 = 1.f / l1;
    float* Ob = O + (size_t)(b * Tn + qrow) * Cn + hsoff;
    #pragma unroll
    for (int nf = 0; nf < 4; nf++) {
        int c = nf * 8 + 2 * t;
        *(float2*)&Ob[(size_t)g       * Cn + c] = make_float2(oa[nf][0] * i0, oa[nf][1] * i0);
        *(float2*)&Ob[(size_t)(g + 8) * Cn + c] = make_float2(oa[nf][2] * i1, oa[nf][3] * i1);
    }
}

// ---------------- Residual add + LayerNorm ----------------
__global__ __launch_bounds__(256) void add_ln_kernel(
    float* __restrict__ x, const float* __restrict__ t,
    const float* __restrict__ w, const float* __restrict__ bb)
{
    int row = blockIdx.x;
    int c = threadIdx.x;
    float v = x[(size_t)row * Cn + c];
    if (t) v += t[(size_t)row * Cn + c];

    float s = v, s2 = v * v;
    #pragma unroll
    for (int o = 16; o; o >>= 1) {
        s  += __shfl_xor_sync(0xFFFFFFFFu, s, o);
        s2 += __shfl_xor_sync(0xFFFFFFFFu, s2, o);
    }
    __shared__ float sh[16];
    int warp = c >> 5, lane = c & 31;
    if (lane == 0) { sh[warp] = s; sh[warp + 8] = s2; }
    __syncthreads();
    float sum = 0.f, sum2 = 0.f;
    #pragma unroll
    for (int i = 0; i < 8; i++) { sum += sh[i]; sum2 += sh[i + 8]; }

    float mean = sum * (1.f / Cn);
    float var  = sum2 * (1.f / Cn) - mean * mean;
    float r = rsqrtf(var + EPSF);
    x[(size_t)row * Cn + c] = (v - mean) * r * w[c] + bb[c];
}

// ---------------- Loss ----------------
__global__ __launch_bounds__(256) void loss_row_kernel(
    const float* __restrict__ logits, const int* __restrict__ target,
    float* __restrict__ nll)
{
    int gwarp = (blockIdx.x * blockDim.x + threadIdx.x) >> 5;
    int lane = threadIdx.x & 31;
    if (gwarp >= NROWS) return;
    const float* lg = logits + (size_t)gwarp * Vn;
    float v0 = lg[lane], v1 = lg[lane + 32], v2 = lg[lane + 64];
    float mx = fmaxf(v0, fmaxf(v1, v2));
    #pragma unroll
    for (int o = 16; o; o >>= 1) mx = fmaxf(mx, __shfl_xor_sync(0xFFFFFFFFu, mx, o));
    float s = __expf(v0 - mx) + __expf(v1 - mx) + __expf(v2 - mx);
    #pragma unroll
    for (int o = 16; o; o >>= 1) s += __shfl_xor_sync(0xFFFFFFFFu, s, o);
    if (lane == 0) {
        float lse = mx + logf(s);
        nll[gwarp] = lse - lg[target[gwarp]];
    }
}

__global__ __launch_bounds__(256) void loss_reduce_kernel(
    const float* __restrict__ nll, float* __restrict__ out)
{
    __shared__ float sh[256];
    float s = 0.f;
    for (int i = threadIdx.x; i < NROWS; i += 256) s += nll[i];
    sh[threadIdx.x] = s;
    __syncthreads();
    for (int st = 128; st; st >>= 1) {
        if (threadIdx.x < st) sh[threadIdx.x] += sh[threadIdx.x + st];
        __syncthreads();
    }
    if (threadIdx.x == 0) out[0] = sh[0] * (1.f / NROWS);
}

// ---------------- Host-side launch sequence (graph-capturable) ----------------
extern "C" void kernel_launch(void* const* d_in, const int* in_sizes, int n_in,
                              void* d_out, int out_size) {
    const int*   idx    = (const int*)  d_in[0];
    const int*   target = (const int*)  d_in[1];
    const float* tok    = (const float*)d_in[2];
    const float* pos    = (const float*)d_in[3];
    const float* Wq     = (const float*)d_in[4];
    const float* Wk     = (const float*)d_in[5];
    const float* Wv     = (const float*)d_in[6];
    const float* Wo     = (const float*)d_in[7];
    const float* bo     = (const float*)d_in[8];
    const float* W1     = (const float*)d_in[9];
    const float* b1     = (const float*)d_in[10];
    const float* W2     = (const float*)d_in[11];
    const float* b2     = (const float*)d_in[12];
    const float* ln1w   = (const float*)d_in[13];
    const float* ln1b   = (const float*)d_in[14];
    const float* ln2w   = (const float*)d_in[15];
    const float* ln2b   = (const float*)d_in[16];
    const float* lnfw   = (const float*)d_in[17];
    const float* lnfb   = (const float*)d_in[18];
    const float* Wlm    = (const float*)d_in[19];
    const float* blm    = (const float*)d_in[20];

    float* logits = (float*)d_out;

    float* s = nullptr;
    cudaGetSymbolAddress((void**)&s, g_scratch);
    float* x   = s;
    float* ba  = s + 1 * (size_t)NROWS * Cn;
    float* bb  = s + 2 * (size_t)NROWS * Cn;   // K^T lives here
    float* bc  = s + 3 * (size_t)NROWS * Cn;
    float* bd  = s + 4 * (size_t)NROWS * Cn;
    float* nll = s + 5 * (size_t)NROWS * Cn;

    cudaFuncSetAttribute(gemm_tc_kernel,
                         cudaFuncAttributeMaxDynamicSharedMemorySize, GSMEM);
    cudaFuncSetAttribute(gemm_qkv_kernel,
                         cudaFuncAttributeMaxDynamicSharedMemorySize, GSMEM);

    dim3 gemmGridC(Cn / 64, NROWS / 128);          // (4, 128)
    dim3 gemmGridV((Vn + 63) / 64, NROWS / 128);   // (2, 128)
    dim3 qkvGrid(Cn / 64, NROWS / 128, 3);         // (4, 128, 3)
    dim3 attnGrid(4, Hn, Bn);

    embed_kernel<<<NROWS, 256>>>(idx, tok, pos, x);

    for (int l = 0; l < Ln; l++) {
        const float* wq = Wq + (size_t)l * CC;
        const float* wk = Wk + (size_t)l * CC;
        const float* wv = Wv + (size_t)l * CC;
        const float* wo = Wo + (size_t)l * CC;
        const float* w1 = W1 + (size_t)l * CC;
        const float* w2 = W2 + (size_t)l * CC;

        gemm_qkv_kernel<<<qkvGrid, 256, GSMEM>>>(x, wq, wk, wv, ba, bb, bc);

        attn_tc_kernel<<<attnGrid, 128>>>(ba, bb, bc, bd);

        gemm_tc_kernel<<<gemmGridC, 256, GSMEM>>>(bd, wo, bo + (size_t)l * Cn, ba, Cn, 0, 0);
        add_ln_kernel<<<NROWS, 256>>>(x, ba, ln1w + (size_t)l * Cn, ln1b + (size_t)l * Cn);

        gemm_tc_kernel<<<gemmGridC, 256, GSMEM>>>(x, w1, b1 + (size_t)l * Cn, bb, Cn, 1, 0);
        gemm_tc_kernel<<<gemmGridC, 256, GSMEM>>>(bb, w2, b2 + (size_t)l * Cn, bc, Cn, 0, 0);
        add_ln_kernel<<<NROWS, 256>>>(x, bc, ln2w + (size_t)l * Cn, ln2b + (size_t)l * Cn);
    }

    add_ln_kernel<<<NROWS, 256>>>(x, nullptr, lnfw, lnfb);
    gemm_tc_kernel<<<gemmGridV, 256, GSMEM>>>(x, Wlm, blm, logits, Vn, 0, 0);

    if (out_size > NROWS * Vn) {
        loss_row_kernel<<<NROWS / 8, 256>>>(logits, target, nll);
        loss_reduce_kernel<<<1, 256>>>(nll, logits + (size_t)NROWS * Vn);
    }
}

// round 13
// speedup vs baseline: 1.0017x; 1.0017x over previous
#include <cuda_runtime.h>
#include <cuda_bf16.h>

// ---------------- Problem constants ----------------
#define Bn    64
#define Tn    256
#define Cn    256
#define Hn    8
#define HSn   32         // head size
#define Ln    6
#define Vn    96
#define NROWS (Bn*Tn)    // 16384
#define CC    (Cn*Cn)    // 65536
#define EPSF  1e-5f
#define KK    256        // K dim of every GEMM

// ---------------- Scratch (static device memory; no allocation) ----------------
__device__ float g_scratch[5 * NROWS * Cn + NROWS];

// ---------------- Embedding ----------------
__global__ void embed_kernel(const int* __restrict__ idx,
                             const float* __restrict__ tok,
                             const float* __restrict__ pos,
                             float* __restrict__ x) {
    int row = blockIdx.x;
    int c = threadIdx.x;
    int token = idx[row];
    x[row * Cn + c] = tok[token * Cn + c] + pos[(row & (Tn - 1)) * Cn + c];
}

// ---------------- tf32 helpers ----------------
__device__ __forceinline__ unsigned f2tf(float f) {
    unsigned u;
    asm("cvt.rna.tf32.f32 %0, %1;" : "=r"(u) : "f"(f));
    return u;
}

__device__ __forceinline__ void mma_tf32(float* d, const unsigned* a, const unsigned* b) {
    asm volatile("mma.sync.aligned.m16n8k8.row.col.f32.tf32.tf32.f32 "
        "{%0,%1,%2,%3}, {%4,%5,%6,%7}, {%8,%9}, {%0,%1,%2,%3};"
        : "+f"(d[0]), "+f"(d[1]), "+f"(d[2]), "+f"(d[3])
        : "r"(a[0]), "r"(a[1]), "r"(a[2]), "r"(a[3]), "r"(b[0]), "r"(b[1]));
}

// ---------------- Tensor-core tf32 GEMM (fragment-ordered smem) ----------------
// Cout[M,Nd] = A[M,256] @ W[256,Nd] (+bias)(+relu). CTA 128x64, BK=32,
// 8 warps (4M x 2N), warp tile 32x32.
// Shared memory holds each mma tile in FRAGMENT order:
//   A tile (m16k8), tile idx = mt*4+ks, elem = lane*4 + reg (reg=half*2+i2)
//   B tile (k8n8),  tile idx = ks*8+nt, elem = (g*4+t)*2 + half
// so fragment loads are 2xLDS.128 + 4xLDS.64 per kstep, conflict-free.
#define APAD 132
#define BPAD 66
#define A_BUF (32*APAD)   // 4224 u32 (8 mt x 4 ks tiles)
#define B_BUF (32*BPAD)   // 2112 u32 (4 ks x 8 nt tiles)
#define GSMEM ((2*A_BUF + 2*B_BUF) * 4)   // 50688 bytes

__device__ __forceinline__ void gemm_core(
    const float* __restrict__ A, const float* __restrict__ W,
    const float* __restrict__ bias, float* __restrict__ Cout,
    int Nd, int relu, int transT, unsigned* gsm)
{
    const int tid = threadIdx.x;
    const int lane = tid & 31, warp = tid >> 5;
    const int g = lane >> 2, t = lane & 3;
    const int wm = (warp & 3) * 32, wn = (warp >> 2) * 32;
    const int mt0 = (warp & 3) * 2;
    const int nt0 = (warp >> 2) * 4;
    const int aRowBase = blockIdx.y * 128;
    const int bColBase = blockIdx.x * 64;

    float acc[2][4][4] = {};
    float4 ar[4];
    float4 br[2];

    // per-thread constant offsets
    int aGrow[4], aSoff[4];
    const int aGcol0 = (tid & 7) << 2;
    #pragma unroll
    for (int i = 0; i < 4; i++) {
        int fi = tid + i * 256;
        int r = fi >> 3;
        aGrow[i] = r;
        int mt = r >> 4, rr = r & 15;
        int ks = aGcol0 >> 3, half = (aGcol0 >> 2) & 1;
        aSoff[i] = (mt * 4 + ks) * APAD + (rr & 7) * 16 + half * 2 + (rr >> 3);
    }
    int bGrow[2], bSoff[2];
    const int bGcol0 = (tid & 15) << 2;
    #pragma unroll
    for (int i = 0; i < 2; i++) {
        int fi = tid + i * 256;
        int r = fi >> 4;
        bGrow[i] = r;
        int ks = r >> 3, kk = r & 7;
        int nt = bGcol0 >> 3, g0 = bGcol0 & 7;
        bSoff[i] = (ks * 8 + nt) * BPAD + g0 * 8 + (kk & 3) * 2 + (kk >> 2);
    }
    const int wcol = bColBase + bGcol0;

    // prologue: prefetch chunk 0
    #pragma unroll
    for (int i = 0; i < 4; i++)
        ar[i] = *(const float4*)(A + (size_t)(aRowBase + aGrow[i]) * KK + aGcol0);
    #pragma unroll
    for (int i = 0; i < 2; i++)
        br[i] = (wcol < Nd) ? *(const float4*)(W + (size_t)bGrow[i] * Nd + wcol)
                            : make_float4(0.f, 0.f, 0.f, 0.f);
    // store chunk 0 into buffer 0 (fragment order)
    {
        unsigned* Asb = gsm;
        unsigned* Bsb = gsm + 2 * A_BUF;
        #pragma unroll
        for (int i = 0; i < 4; i++) {
            unsigned* p = Asb + aSoff[i];
            p[0]  = f2tf(ar[i].x); p[4]  = f2tf(ar[i].y);
            p[8]  = f2tf(ar[i].z); p[12] = f2tf(ar[i].w);
        }
        #pragma unroll
        for (int i = 0; i < 2; i++) {
            unsigned* p = Bsb + bSoff[i];
            p[0]  = f2tf(br[i].x); p[8]  = f2tf(br[i].y);
            p[16] = f2tf(br[i].z); p[24] = f2tf(br[i].w);
        }
    }
    __syncthreads();

    for (int kt = 0; kt < 8; kt++) {
        int cur = kt & 1;
        const unsigned* As = gsm + cur * A_BUF;
        const unsigned* Bs = gsm + 2 * A_BUF + cur * B_BUF;

        // prefetch next chunk (global) — overlaps compute below
        if (kt < 7) {
            int kn = (kt + 1) * 32;
            #pragma unroll
            for (int i = 0; i < 4; i++)
                ar[i] = *(const float4*)(A + (size_t)(aRowBase + aGrow[i]) * KK + kn + aGcol0);
            #pragma unroll
            for (int i = 0; i < 2; i++)
                br[i] = (wcol < Nd) ? *(const float4*)(W + (size_t)(kn + bGrow[i]) * Nd + wcol)
                                    : make_float4(0.f, 0.f, 0.f, 0.f);
        }

        // compute: 4 ksteps, fragment loads are vectorized & conflict-free
        #pragma unroll
        for (int ks = 0; ks < 4; ks++) {
            uint4 af[2];
            uint2 bf[4];
            af[0] = *(const uint4*)&As[((mt0    ) * 4 + ks) * APAD + lane * 4];
            af[1] = *(const uint4*)&As[((mt0 + 1) * 4 + ks) * APAD + lane * 4];
            #pragma unroll
            for (int j = 0; j < 4; j++)
                bf[j] = *(const uint2*)&Bs[(ks * 8 + nt0 + j) * BPAD + g * 8 + t * 2];
            #pragma unroll
            for (int i = 0; i < 2; i++)
                #pragma unroll
                for (int j = 0; j < 4; j++)
                    mma_tf32(acc[i][j], (const unsigned*)&af[i], (const unsigned*)&bf[j]);
        }

        // store prefetched chunk into the other buffer
        if (kt < 7) {
            unsigned* Asn = gsm + (1 - cur) * A_BUF;
            unsigned* Bsn = gsm + 2 * A_BUF + (1 - cur) * B_BUF;
            #pragma unroll
            for (int i = 0; i < 4; i++) {
                unsigned* p = Asn + aSoff[i];
                p[0]  = f2tf(ar[i].x); p[4]  = f2tf(ar[i].y);
                p[8]  = f2tf(ar[i].z); p[12] = f2tf(ar[i].w);
            }
            #pragma unroll
            for (int i = 0; i < 2; i++) {
                unsigned* p = Bsn + bSoff[i];
                p[0]  = f2tf(br[i].x); p[8]  = f2tf(br[i].y);
                p[16] = f2tf(br[i].z); p[24] = f2tf(br[i].w);
            }
        }
        __syncthreads();
    }

    if (!transT) {
        #pragma unroll
        for (int i = 0; i < 2; i++) {
            #pragma unroll
            for (int j = 0; j < 4; j++) {
                int col = bColBase + wn + j * 8 + t * 2;
                if (col >= Nd) continue;
                float bx = 0.f, by = 0.f;
                if (bias) { bx = bias[col]; by = bias[col + 1]; }
                int r0 = aRowBase + wm + i * 16 + g;
                float v0 = acc[i][j][0] + bx, v1 = acc[i][j][1] + by;
                float v2 = acc[i][j][2] + bx, v3 = acc[i][j][3] + by;
                if (relu) {
                    v0 = fmaxf(v0, 0.f); v1 = fmaxf(v1, 0.f);
                    v2 = fmaxf(v2, 0.f); v3 = fmaxf(v3, 0.f);
                }
                *(float2*)&Cout[(size_t)r0 * Nd + col]       = make_float2(v0, v1);
                *(float2*)&Cout[(size_t)(r0 + 8) * Nd + col] = make_float2(v2, v3);
            }
        }
    } else {
        // transposed epilogue: out[b][c][t], per-warp smem transpose patch
        float* patch = (float*)gsm + warp * 1056;   // 32 cols x 32 rows, stride 33
        #pragma unroll
        for (int i = 0; i < 2; i++) {
            #pragma unroll
            for (int j = 0; j < 4; j++) {
                int c0 = j * 8 + t * 2;
                int r0 = i * 16 + g;
                patch[(c0    ) * 33 + r0    ] = acc[i][j][0];
                patch[(c0 + 1) * 33 + r0    ] = acc[i][j][1];
                patch[(c0    ) * 33 + r0 + 8] = acc[i][j][2];
                patch[(c0 + 1) * 33 + r0 + 8] = acc[i][j][3];
            }
        }
        __syncwarp();
        int rowG = aRowBase + wm;
        int bIdx = rowG >> 8;
        int tg = (lane & 7) * 4;
        int chi = lane >> 3;
        int tBase = (rowG & 255) + tg;
        #pragma unroll
        for (int jj = 0; jj < 8; jj++) {
            int c = jj * 4 + chi;
            float4 v;
            v.x = patch[c * 33 + tg + 0];
            v.y = patch[c * 33 + tg + 1];
            v.z = patch[c * 33 + tg + 2];
            v.w = patch[c * 33 + tg + 3];
            *(float4*)&Cout[(size_t)bIdx * (Cn * Tn) +
                            (size_t)(bColBase + wn + c) * Tn + tBase] = v;
        }
    }
}

__global__ __launch_bounds__(256, 2) void gemm_tc_kernel(
    const float* __restrict__ A, const float* __restrict__ W,
    const float* __restrict__ bias, float* __restrict__ Cout,
    int Nd, int relu, int transT)
{
    extern __shared__ unsigned gsm[];
    gemm_core(A, W, bias, Cout, Nd, relu, transT, gsm);
}

// fused Q/K/V projections: blockIdx.z selects weight/output; K written transposed
__global__ __launch_bounds__(256, 2) void gemm_qkv_kernel(
    const float* __restrict__ A,
    const float* __restrict__ Wq, const float* __restrict__ Wk,
    const float* __restrict__ Wv,
    float* __restrict__ oq, float* __restrict__ okt, float* __restrict__ ov)
{
    extern __shared__ unsigned gsm[];
    int z = blockIdx.z;
    const float* W = (z == 0) ? Wq : (z == 1) ? Wk : Wv;
    float*       o = (z == 0) ? oq : (z == 1) ? okt : ov;
    gemm_core(A, W, nullptr, o, Cn, 0, (z == 1) ? 1 : 0, gsm);
}

// ---------------- Tensor-core flash attention ----------------
#define KSTR 72
#define VSTR 40
#define PSTR 68

__global__ __launch_bounds__(128, 4) void attn_tc_kernel(
    const float* __restrict__ Q,    // [B*T, C]
    const float* __restrict__ KT,   // [B][C][T]
    const float* __restrict__ V,    // [B*T, C]
    float* __restrict__ O)          // [B*T, C]
{
    __shared__ unsigned Ks[32 * KSTR];
    __shared__ unsigned Vs[64 * VSTR];
    __shared__ unsigned Ps[4][16 * PSTR];

    int qb = 3 - blockIdx.x;          // heavy blocks first
    int h  = blockIdx.y;
    int b  = blockIdx.z;
    int tid = threadIdx.x;
    int warp = tid >> 5, lane = tid & 31;
    int g = lane >> 2, t = lane & 3;
    int hsoff = h * HSn;
    int q0 = qb * 64;
    int qrow = q0 + warp * 16;

    unsigned qa[4][4];
    {
        const float* Qb = Q + (size_t)(b * Tn + qrow) * Cn + hsoff;
        #pragma unroll
        for (int ks = 0; ks < 4; ks++) {
            qa[ks][0] = f2tf(Qb[(size_t)g       * Cn + ks * 8 + t    ] * 0.0625f);
            qa[ks][1] = f2tf(Qb[(size_t)(g + 8) * Cn + ks * 8 + t    ] * 0.0625f);
            qa[ks][2] = f2tf(Qb[(size_t)g       * Cn + ks * 8 + t + 4] * 0.0625f);
            qa[ks][3] = f2tf(Qb[(size_t)(g + 8) * Cn + ks * 8 + t + 4] * 0.0625f);
        }
    }

    float oa[4][4] = {};
    float m0 = -1e30f, m1 = -1e30f, l0 = 0.f, l1 = 0.f;

    const float* KTb = KT + (size_t)b * (Cn * Tn) + (size_t)hsoff * Tn;
    const float* Vb  = V  + (size_t)(b * Tn) * Cn + hsoff;
    unsigned* Pw = Ps[warp];

    for (int kc = 0; kc <= qb; kc++) {
        __syncthreads();
        #pragma unroll
        for (int i = 0; i < 4; i++) {
            int fi = tid + i * 128;
            int r = fi >> 4, c4 = (fi & 15) << 2;
            float4 v = *(const float4*)(KTb + (size_t)r * Tn + kc * 64 + c4);
            uint4 u = { f2tf(v.x), f2tf(v.y), f2tf(v.z), f2tf(v.w) };
            *(uint4*)&Ks[r * KSTR + c4] = u;
        }
        #pragma unroll
        for (int i = 0; i < 4; i++) {
            int fi = tid + i * 128;
            int r = fi >> 3, c4 = (fi & 7) << 2;
            float4 v = *(const float4*)(Vb + (size_t)(kc * 64 + r) * Cn + c4);
            uint4 u = { f2tf(v.x), f2tf(v.y), f2tf(v.z), f2tf(v.w) };
            *(uint4*)&Vs[r * VSTR + c4] = u;
        }
        __syncthreads();

        float sc[8][4];
        #pragma unroll
        for (int nf = 0; nf < 8; nf++)
            #pragma unroll
            for (int j = 0; j < 4; j++) sc[nf][j] = 0.f;
        #pragma unroll
        for (int ks = 0; ks < 4; ks++) {
            #pragma unroll
            for (int nf = 0; nf < 8; nf++) {
                unsigned bf[2];
                bf[0] = Ks[(ks * 8 + t    ) * KSTR + nf * 8 + g];
                bf[1] = Ks[(ks * 8 + t + 4) * KSTR + nf * 8 + g];
                mma_tf32(sc[nf], qa[ks], bf);
            }
        }

        if (kc == qb) {
            int r0 = warp * 16 + g;
            #pragma unroll
            for (int nf = 0; nf < 8; nf++) {
                int c0 = nf * 8 + 2 * t;
                if (c0     > r0    ) sc[nf][0] = -1e30f;
                if (c0 + 1 > r0    ) sc[nf][1] = -1e30f;
                if (c0     > r0 + 8) sc[nf][2] = -1e30f;
                if (c0 + 1 > r0 + 8) sc[nf][3] = -1e30f;
            }
        }

        float mx0 = -1e30f, mx1 = -1e30f;
        #pragma unroll
        for (int nf = 0; nf < 8; nf++) {
            mx0 = fmaxf(mx0, fmaxf(sc[nf][0], sc[nf][1]));
            mx1 = fmaxf(mx1, fmaxf(sc[nf][2], sc[nf][3]));
        }
        #pragma unroll
        for (int o = 1; o <= 2; o <<= 1) {
            mx0 = fmaxf(mx0, __shfl_xor_sync(0xFFFFFFFFu, mx0, o));
            mx1 = fmaxf(mx1, __shfl_xor_sync(0xFFFFFFFFu, mx1, o));
        }
        float nm0 = fmaxf(m0, mx0), nm1 = fmaxf(m1, mx1);
        float al0 = __expf(m0 - nm0), al1 = __expf(m1 - nm1);

        float s0 = 0.f, s1 = 0.f;
        #pragma unroll
        for (int nf = 0; nf < 8; nf++) {
            float p0 = __expf(sc[nf][0] - nm0);
            float p1 = __expf(sc[nf][1] - nm0);
            float p2 = __expf(sc[nf][2] - nm1);
            float p3 = __expf(sc[nf][3] - nm1);
            s0 += p0 + p1; s1 += p2 + p3;
            uint2 u01 = make_uint2(f2tf(p0), f2tf(p1));
            uint2 u23 = make_uint2(f2tf(p2), f2tf(p3));
            *(uint2*)&Pw[(g    ) * PSTR + nf * 8 + 2 * t] = u01;
            *(uint2*)&Pw[(g + 8) * PSTR + nf * 8 + 2 * t] = u23;
        }
        #pragma unroll
        for (int o = 1; o <= 2; o <<= 1) {
            s0 += __shfl_xor_sync(0xFFFFFFFFu, s0, o);
            s1 += __shfl_xor_sync(0xFFFFFFFFu, s1, o);
        }
        l0 = l0 * al0 + s0;
        l1 = l1 * al1 + s1;
        m0 = nm0; m1 = nm1;

        #pragma unroll
        for (int nf = 0; nf < 4; nf++) {
            oa[nf][0] *= al0; oa[nf][1] *= al0;
            oa[nf][2] *= al1; oa[nf][3] *= al1;
        }
        __syncwarp();

        #pragma unroll
        for (int ks = 0; ks < 8; ks++) {
            unsigned pa[4];
            pa[0] = Pw[(g    ) * PSTR + ks * 8 + t    ];
            pa[1] = Pw[(g + 8) * PSTR + ks * 8 + t    ];
            pa[2] = Pw[(g    ) * PSTR + ks * 8 + t + 4];
            pa[3] = Pw[(g + 8) * PSTR + ks * 8 + t + 4];
            #pragma unroll
            for (int nf = 0; nf < 4; nf++) {
                unsigned vb[2];
                vb[0] = Vs[(ks * 8 + t    ) * VSTR + nf * 8 + g];
                vb[1] = Vs[(ks * 8 + t + 4) * VSTR + nf * 8 + g];
                mma_tf32(oa[nf], pa, vb);
            }
        }
    }

    float i0 = 1.f / l0, i1 = 1.f / l1;
    float* Ob = O + (size_t)(b * Tn + qrow) * Cn + hsoff;
    #pragma unroll
    for (int nf = 0; nf < 4; nf++) {
        int c = nf * 8 + 2 * t;
        *(float2*)&Ob[(size_t)g       * Cn + c] = make_float2(oa[nf][0] * i0, oa[nf][1] * i0);
        *(float2*)&Ob[(size_t)(g + 8) * Cn + c] = make_float2(oa[nf][2] * i1, oa[nf][3] * i1);
    }
}

// ---------------- Residual add + LayerNorm ----------------
__global__ __launch_bounds__(256) void add_ln_kernel(
    float* __restrict__ x, const float* __restrict__ t,
    const float* __restrict__ w, const float* __restrict__ bb)
{
    int row = blockIdx.x;
    int c = threadIdx.x;
    float v = x[(size_t)row * Cn + c];
    if (t) v += t[(size_t)row * Cn + c];

    float s = v, s2 = v * v;
    #pragma unroll
    for (int o = 16; o; o >>= 1) {
        s  += __shfl_xor_sync(0xFFFFFFFFu, s, o);
        s2 += __shfl_xor_sync(0xFFFFFFFFu, s2, o);
    }
    __shared__ float sh[16];
    int warp = c >> 5, lane = c & 31;
    if (lane == 0) { sh[warp] = s; sh[warp + 8] = s2; }
    __syncthreads();
    float sum = 0.f, sum2 = 0.f;
    #pragma unroll
    for (int i = 0; i < 8; i++) { sum += sh[i]; sum2 += sh[i + 8]; }

    float mean = sum * (1.f / Cn);
    float var  = sum2 * (1.f / Cn) - mean * mean;
    float r = rsqrtf(var + EPSF);
    x[(size_t)row * Cn + c] = (v - mean) * r * w[c] + bb[c];
}

// ---------------- Loss ----------------
__global__ __launch_bounds__(256) void loss_row_kernel(
    const float* __restrict__ logits, const int* __restrict__ target,
    float* __restrict__ nll)
{
    int gwarp = (blockIdx.x * blockDim.x + threadIdx.x) >> 5;
    int lane = threadIdx.x & 31;
    if (gwarp >= NROWS) return;
    const float* lg = logits + (size_t)gwarp * Vn;
    float v0 = lg[lane], v1 = lg[lane + 32], v2 = lg[lane + 64];
    float mx = fmaxf(v0, fmaxf(v1, v2));
    #pragma unroll
    for (int o = 16; o; o >>= 1) mx = fmaxf(mx, __shfl_xor_sync(0xFFFFFFFFu, mx, o));
    float s = __expf(v0 - mx) + __expf(v1 - mx) + __expf(v2 - mx);
    #pragma unroll
    for (int o = 16; o; o >>= 1) s += __shfl_xor_sync(0xFFFFFFFFu, s, o);
    if (lane == 0) {
        float lse = mx + logf(s);
        nll[gwarp] = lse - lg[target[gwarp]];
    }
}

__global__ __launch_bounds__(256) void loss_reduce_kernel(
    const float* __restrict__ nll, float* __restrict__ out)
{
    __shared__ float sh[256];
    float s = 0.f;
    for (int i = threadIdx.x; i < NROWS; i += 256) s += nll[i];
    sh[threadIdx.x] = s;
    __syncthreads();
    for (int st = 128; st; st >>= 1) {
        if (threadIdx.x < st) sh[threadIdx.x] += sh[threadIdx.x + st];
        __syncthreads();
    }
    if (threadIdx.x == 0) out[0] = sh[0] * (1.f / NROWS);
}

// ---------------- Host-side launch sequence (graph-capturable) ----------------
extern "C" void kernel_launch(void* const* d_in, const int* in_sizes, int n_in,
                              void* d_out, int out_size) {
    const int*   idx    = (const int*)  d_in[0];
    const int*   target = (const int*)  d_in[1];
    const float* tok    = (const float*)d_in[2];
    const float* pos    = (const float*)d_in[3];
    const float* Wq     = (const float*)d_in[4];
    const float* Wk     = (const float*)d_in[5];
    const float* Wv     = (const float*)d_in[6];
    const float* Wo     = (const float*)d_in[7];
    const float* bo     = (const float*)d_in[8];
    const float* W1     = (const float*)d_in[9];
    const float* b1     = (const float*)d_in[10];
    const float* W2     = (const float*)d_in[11];
    const float* b2     = (const float*)d_in[12];
    const float* ln1w   = (const float*)d_in[13];
    const float* ln1b   = (const float*)d_in[14];
    const float* ln2w   = (const float*)d_in[15];
    const float* ln2b   = (const float*)d_in[16];
    const float* lnfw   = (const float*)d_in[17];
    const float* lnfb   = (const float*)d_in[18];
    const float* Wlm    = (const float*)d_in[19];
    const float* blm    = (const float*)d_in[20];

    float* logits = (float*)d_out;

    float* s = nullptr;
    cudaGetSymbolAddress((void**)&s, g_scratch);
    float* x   = s;
    float* ba  = s + 1 * (size_t)NROWS * Cn;
    float* bb  = s + 2 * (size_t)NROWS * Cn;   // K^T lives here
    float* bc  = s + 3 * (size_t)NROWS * Cn;
    float* bd  = s + 4 * (size_t)NROWS * Cn;
    float* nll = s + 5 * (size_t)NROWS * Cn;

    cudaFuncSetAttribute(gemm_tc_kernel,
                         cudaFuncAttributeMaxDynamicSharedMemorySize, GSMEM);
    cudaFuncSetAttribute(gemm_qkv_kernel,
                         cudaFuncAttributeMaxDynamicSharedMemorySize, GSMEM);

    dim3 gemmGridC(Cn / 64, NROWS / 128);          // (4, 128)
    dim3 gemmGridV((Vn + 63) / 64, NROWS / 128);   // (2, 128)
    dim3 qkvGrid(Cn / 64, NROWS / 128, 3);         // (4, 128, 3)
    dim3 attnGrid(4, Hn, Bn);

    embed_kernel<<<NROWS, 256>>>(idx, tok, pos, x);

    for (int l = 0; l < Ln; l++) {
        const float* wq = Wq + (size_t)l * CC;
        const float* wk = Wk + (size_t)l * CC;
        const float* wv = Wv + (size_t)l * CC;
        const float* wo = Wo + (size_t)l * CC;
        const float* w1 = W1 + (size_t)l * CC;
        const float* w2 = W2 + (size_t)l * CC;

        gemm_qkv_kernel<<<qkvGrid, 256, GSMEM>>>(x, wq, wk, wv, ba, bb, bc);

        attn_tc_kernel<<<attnGrid, 128>>>(ba, bb, bc, bd);

        gemm_tc_kernel<<<gemmGridC, 256, GSMEM>>>(bd, wo, bo + (size_t)l * Cn, ba, Cn, 0, 0);
        add_ln_kernel<<<NROWS, 256>>>(x, ba, ln1w + (size_t)l * Cn, ln1b + (size_t)l * Cn);

        gemm_tc_kernel<<<gemmGridC, 256, GSMEM>>>(x, w1, b1 + (size_t)l * Cn, bb, Cn, 1, 0);
        gemm_tc_kernel<<<gemmGridC, 256, GSMEM>>>(bb, w2, b2 + (size_t)l * Cn, bc, Cn, 0, 0);
        add_ln_kernel<<<NROWS, 256>>>(x, bc, ln2w + (size_t)l * Cn, ln2b + (size_t)l * Cn);
    }

    add_ln_kernel<<<NROWS, 256>>>(x, nullptr, lnfw, lnfb);
    gemm_tc_kernel<<<gemmGridV, 256, GSMEM>>>(x, Wlm, blm, logits, Vn, 0, 0);

    if (out_size > NROWS * Vn) {
        loss_row_kernel<<<NROWS / 8, 256>>>(logits, target, nll);
        loss_reduce_kernel<<<1, 256>>>(nll, logits + (size_t)NROWS * Vn);
    }
}

// round 14
// speedup vs baseline: 1.2111x; 1.2090x over previous
#include <cuda_runtime.h>
#include <cuda_bf16.h>

// ---------------- Problem constants ----------------
#define Bn    64
#define Tn    256
#define Cn    256
#define Hn    8
#define HSn   32         // head size
#define Ln    6
#define Vn    96
#define NROWS (Bn*Tn)    // 16384
#define CC    (Cn*Cn)    // 65536
#define EPSF  1e-5f
#define KK    256

// ---------------- Scratch (static device memory; no allocation) ----------------
__device__ float    g_scratch[4 * NROWS * Cn + NROWS];        // x, ba, bb(KT), bc, nll
__device__ unsigned g_shadow [3 * NROWS * Cn];                 // xs, bds, bbs (tf32)
__device__ unsigned g_wt     [36 * CC + 128 * 256];            // tf32 W^T, lm padded to 128 rows

// ---------------- helpers ----------------
__device__ __forceinline__ unsigned f2tf(float f) {
    unsigned u;
    asm("cvt.rna.tf32.f32 %0, %1;" : "=r"(u) : "f"(f));
    return u;
}
__device__ __forceinline__ void mma_tf32(float* d, const unsigned* a, const unsigned* b) {
    asm volatile("mma.sync.aligned.m16n8k8.row.col.f32.tf32.tf32.f32 "
        "{%0,%1,%2,%3}, {%4,%5,%6,%7}, {%8,%9}, {%0,%1,%2,%3};"
        : "+f"(d[0]), "+f"(d[1]), "+f"(d[2]), "+f"(d[3])
        : "r"(a[0]), "r"(a[1]), "r"(a[2]), "r"(a[3]), "r"(b[0]), "r"(b[1]));
}
__device__ __forceinline__ void ldsm4(unsigned* r, unsigned addr) {
    asm volatile("ldmatrix.sync.aligned.m8n8.x4.shared.b16 {%0,%1,%2,%3}, [%4];"
        : "=r"(r[0]), "=r"(r[1]), "=r"(r[2]), "=r"(r[3]) : "r"(addr));
}
__device__ __forceinline__ void cp16(unsigned dst, const void* src) {
    asm volatile("cp.async.cg.shared.global [%0], [%1], 16;" :: "r"(dst), "l"(src) : "memory");
}
__device__ __forceinline__ unsigned smem_u32(const void* p) {
    return (unsigned)__cvta_generic_to_shared(p);
}

// ---------------- Weight pre-pass: Wt[n][k] = tf32(W[k][n]) ----------------
// grid (8, 8, 37), block (32, 8). Mat 36 = Wlm (256x96 -> 128x256 padded with zeros).
__global__ void wt_kernel(const float* __restrict__ Wq, const float* __restrict__ Wk,
                          const float* __restrict__ Wv, const float* __restrict__ Wo,
                          const float* __restrict__ W1, const float* __restrict__ W2,
                          const float* __restrict__ Wlm, unsigned* __restrict__ wt)
{
    __shared__ float tl[32][33];
    int id = blockIdx.z;
    int kt = blockIdx.x * 32, nt = blockIdx.y * 32;
    const float* src;
    unsigned* dst;
    int nsrc;
    if (id < 36) {
        int l = id / 6, m = id % 6;
        const float* bases[6] = {Wq, Wk, Wv, Wo, W1, W2};
        src = bases[m] + (size_t)l * CC;
        dst = wt + (size_t)id * CC;
        nsrc = 256;
    } else {
        if (nt >= 128) return;
        src = Wlm;
        dst = wt + 36 * CC;
        nsrc = 96;
    }
    int tx = threadIdx.x, ty = threadIdx.y;
    #pragma unroll
    for (int i = 0; i < 4; i++) {
        int k = kt + ty * 4 + i;
        int n = nt + tx;
        tl[ty * 4 + i][tx] = (n < nsrc) ? src[(size_t)k * nsrc + n] : 0.f;
    }
    __syncthreads();
    #pragma unroll
    for (int i = 0; i < 4; i++)
        dst[(size_t)(nt + ty * 4 + i) * 256 + kt + tx] = f2tf(tl[tx][ty * 4 + i]);
}

// ---------------- Embedding (fp32 + tf32 shadow) ----------------
__global__ void embed_kernel(const int* __restrict__ idx,
                             const float* __restrict__ tok,
                             const float* __restrict__ pos,
                             float* __restrict__ x, unsigned* __restrict__ xs) {
    int row = blockIdx.x;
    int c = threadIdx.x;
    int token = idx[row];
    float v = tok[token * Cn + c] + pos[(row & (Tn - 1)) * Cn + c];
    x[row * Cn + c] = v;
    xs[row * Cn + c] = f2tf(v);
}

// ---------------- Tensor-core tf32 GEMM: cp.async + ldmatrix ----------------
// Cout[M,Nd] = A[M,256] @ W[256,Nd] (+bias)(+relu). A tf32-shadow, Wt tf32 [n][k].
// CTA 128x64, BK=32, 8 warps (4M x 2N), warp tile 32x32. Double buffered.
#define SSTR 36                      // u32 stride (rows of 32 + pad 4)
#define ABUF_B (128*SSTR*4)          // 18432 B per A buffer
#define BBUF_B (64*SSTR*4)           //  9216 B per B buffer
#define GSMEM  (2*ABUF_B + 2*BBUF_B) // 55296 B

__device__ __forceinline__ void gemm_core(
    const unsigned* __restrict__ A, const unsigned* __restrict__ Wt,
    const float* __restrict__ bias, float* __restrict__ Cout,
    unsigned* __restrict__ shadow, int Nd, int relu, int transT, char* smem)
{
    const unsigned sbase = smem_u32(smem);
    const int tid = threadIdx.x;
    const int lane = tid & 31, warp = tid >> 5;
    const int g = lane >> 2, t = lane & 3;
    const int wm = (warp & 3) * 32, wn = (warp >> 2) * 32;
    const int aRowBase = blockIdx.y * 128;
    const int bColBase = blockIdx.x * 64;

    float acc[2][4][4] = {};

    // cp.async source/dest (per thread)
    const unsigned* aSrc = A  + (size_t)(aRowBase + (tid >> 3)) * 256 + (tid & 7) * 4;
    const unsigned* bSrc = Wt + (size_t)(bColBase + (tid >> 3)) * 256 + (tid & 7) * 4;
    const unsigned aDst = sbase + (tid >> 3) * (SSTR * 4) + (tid & 7) * 16;
    const unsigned bDst = sbase + 2 * ABUF_B + (tid >> 3) * (SSTR * 4) + (tid & 7) * 16;

    // ldmatrix addresses (per lane)
    unsigned aAddr0, aAddr1, bAddr0, bAddr1;
    {
        int l15 = lane & 15, lh = lane >> 4;
        aAddr0 = sbase + ((wm + l15) * SSTR + lh * 4) * 4;
        aAddr1 = aAddr0 + 16 * SSTR * 4;
        int brow = wn + ((lane >> 4) << 3) + (lane & 7);
        int bk = ((lane >> 3) & 1) * 4;
        bAddr0 = sbase + 2 * ABUF_B + (brow * SSTR + bk) * 4;
        bAddr1 = bAddr0 + 16 * SSTR * 4;
    }

    // prologue: chunk 0 -> buffer 0
    #pragma unroll
    for (int i = 0; i < 4; i++) cp16(aDst + i * 32 * SSTR * 4, aSrc + i * 32 * 256);
    #pragma unroll
    for (int i = 0; i < 2; i++) cp16(bDst + i * 32 * SSTR * 4, bSrc + i * 32 * 256);
    asm volatile("cp.async.commit_group;" ::: "memory");

    for (int kt = 0; kt < 8; kt++) {
        int cur = kt & 1;
        asm volatile("cp.async.wait_group 0;" ::: "memory");
        __syncthreads();

        if (kt < 7) {
            int koff = (kt + 1) * 32;
            unsigned ao = (1 - cur) * ABUF_B, bo = (1 - cur) * BBUF_B;
            #pragma unroll
            for (int i = 0; i < 4; i++)
                cp16(aDst + ao + i * 32 * SSTR * 4, aSrc + i * 32 * 256 + koff);
            #pragma unroll
            for (int i = 0; i < 2; i++)
                cp16(bDst + bo + i * 32 * SSTR * 4, bSrc + i * 32 * 256 + koff);
            asm volatile("cp.async.commit_group;" ::: "memory");
        }

        unsigned aob = cur * ABUF_B, bob = cur * BBUF_B;
        #pragma unroll
        for (int ks = 0; ks < 4; ks++) {
            unsigned a0[4], a1[4], b0[4], b1[4];
            ldsm4(a0, aAddr0 + aob + ks * 32);
            ldsm4(a1, aAddr1 + aob + ks * 32);
            ldsm4(b0, bAddr0 + bob + ks * 32);
            ldsm4(b1, bAddr1 + bob + ks * 32);
            mma_tf32(acc[0][0], a0, b0 + 0);
            mma_tf32(acc[0][1], a0, b0 + 2);
            mma_tf32(acc[0][2], a0, b1 + 0);
            mma_tf32(acc[0][3], a0, b1 + 2);
            mma_tf32(acc[1][0], a1, b0 + 0);
            mma_tf32(acc[1][1], a1, b0 + 2);
            mma_tf32(acc[1][2], a1, b1 + 0);
            mma_tf32(acc[1][3], a1, b1 + 2);
        }
    }

    if (!transT) {
        #pragma unroll
        for (int i = 0; i < 2; i++) {
            #pragma unroll
            for (int j = 0; j < 4; j++) {
                int col = bColBase + wn + j * 8 + t * 2;
                if (col >= Nd) continue;
                float bx = 0.f, by = 0.f;
                if (bias) { bx = bias[col]; by = bias[col + 1]; }
                int r0 = aRowBase + wm + i * 16 + g;
                float v0 = acc[i][j][0] + bx, v1 = acc[i][j][1] + by;
                float v2 = acc[i][j][2] + bx, v3 = acc[i][j][3] + by;
                if (relu) {
                    v0 = fmaxf(v0, 0.f); v1 = fmaxf(v1, 0.f);
                    v2 = fmaxf(v2, 0.f); v3 = fmaxf(v3, 0.f);
                }
                if (Cout) {
                    *(float2*)&Cout[(size_t)r0 * Nd + col]       = make_float2(v0, v1);
                    *(float2*)&Cout[(size_t)(r0 + 8) * Nd + col] = make_float2(v2, v3);
                }
                if (shadow) {
                    *(uint2*)&shadow[(size_t)r0 * Nd + col]       = make_uint2(f2tf(v0), f2tf(v1));
                    *(uint2*)&shadow[(size_t)(r0 + 8) * Nd + col] = make_uint2(f2tf(v2), f2tf(v3));
                }
            }
        }
    } else {
        // transposed epilogue: out[b][c][t] fp32, via per-warp smem patch
        __syncthreads();   // all warps done reading smem tiles
        float* patch = (float*)smem + warp * 1056;   // 32 x 32, stride 33
        #pragma unroll
        for (int i = 0; i < 2; i++) {
            #pragma unroll
            for (int j = 0; j < 4; j++) {
                int c0 = j * 8 + t * 2;
                int r0 = i * 16 + g;
                patch[(c0    ) * 33 + r0    ] = acc[i][j][0];
                patch[(c0 + 1) * 33 + r0    ] = acc[i][j][1];
                patch[(c0    ) * 33 + r0 + 8] = acc[i][j][2];
                patch[(c0 + 1) * 33 + r0 + 8] = acc[i][j][3];
            }
        }
        __syncwarp();
        int rowG = aRowBase + wm;
        int bIdx = rowG >> 8;
        int tg = (lane & 7) * 4;
        int chi = lane >> 3;
        int tBase = (rowG & 255) + tg;
        #pragma unroll
        for (int jj = 0; jj < 8; jj++) {
            int c = jj * 4 + chi;
            float4 v;
            v.x = patch[c * 33 + tg + 0];
            v.y = patch[c * 33 + tg + 1];
            v.z = patch[c * 33 + tg + 2];
            v.w = patch[c * 33 + tg + 3];
            *(float4*)&Cout[(size_t)bIdx * (Cn * Tn) +
                            (size_t)(bColBase + wn + c) * Tn + tBase] = v;
        }
    }
}

__global__ __launch_bounds__(256, 3) void gemm_tc_kernel(
    const unsigned* __restrict__ A, const unsigned* __restrict__ Wt,
    const float* __restrict__ bias, float* __restrict__ Cout,
    unsigned* __restrict__ shadow, int Nd, int relu, int transT)
{
    extern __shared__ char gsm[];
    gemm_core(A, Wt, bias, Cout, shadow, Nd, relu, transT, gsm);
}

// fused Q/K/V: blockIdx.z selects weight/output; K written transposed fp32
__global__ __launch_bounds__(256, 3) void gemm_qkv_kernel(
    const unsigned* __restrict__ A, const unsigned* __restrict__ wtBase,
    float* __restrict__ oq, float* __restrict__ okt, float* __restrict__ ov)
{
    extern __shared__ char gsm[];
    int z = blockIdx.z;
    const unsigned* Wt = wtBase + (size_t)z * CC;
    float* o = (z == 0) ? oq : (z == 1) ? okt : ov;
    gemm_core(A, Wt, nullptr, o, nullptr, Cn, 0, (z == 1) ? 1 : 0, gsm);
}

// ---------------- Tensor-core flash attention (writes tf32 shadow) ----------------
#define KSTR 72
#define VSTR 40
#define PSTR 68

__global__ __launch_bounds__(128, 4) void attn_tc_kernel(
    const float* __restrict__ Q,    // [B*T, C]
    const float* __restrict__ KT,   // [B][C][T]
    const float* __restrict__ V,    // [B*T, C]
    unsigned* __restrict__ Os)      // tf32 [B*T, C]
{
    __shared__ unsigned Ks[32 * KSTR];
    __shared__ unsigned Vs[64 * VSTR];
    __shared__ unsigned Ps[4][16 * PSTR];

    int qb = 3 - blockIdx.x;
    int h  = blockIdx.y;
    int b  = blockIdx.z;
    int tid = threadIdx.x;
    int warp = tid >> 5, lane = tid & 31;
    int g = lane >> 2, t = lane & 3;
    int hsoff = h * HSn;
    int qrow = qb * 64 + warp * 16;

    unsigned qa[4][4];
    {
        const float* Qb = Q + (size_t)(b * Tn + qrow) * Cn + hsoff;
        #pragma unroll
        for (int ks = 0; ks < 4; ks++) {
            qa[ks][0] = f2tf(Qb[(size_t)g       * Cn + ks * 8 + t    ] * 0.0625f);
            qa[ks][1] = f2tf(Qb[(size_t)(g + 8) * Cn + ks * 8 + t    ] * 0.0625f);
            qa[ks][2] = f2tf(Qb[(size_t)g       * Cn + ks * 8 + t + 4] * 0.0625f);
            qa[ks][3] = f2tf(Qb[(size_t)(g + 8) * Cn + ks * 8 + t + 4] * 0.0625f);
        }
    }

    float oa[4][4] = {};
    float m0 = -1e30f, m1 = -1e30f, l0 = 0.f, l1 = 0.f;

    const float* KTb = KT + (size_t)b * (Cn * Tn) + (size_t)hsoff * Tn;
    const float* Vb  = V  + (size_t)(b * Tn) * Cn + hsoff;
    unsigned* Pw = Ps[warp];

    for (int kc = 0; kc <= qb; kc++) {
        __syncthreads();
        #pragma unroll
        for (int i = 0; i < 4; i++) {
            int fi = tid + i * 128;
            int r = fi >> 4, c4 = (fi & 15) << 2;
            float4 v = *(const float4*)(KTb + (size_t)r * Tn + kc * 64 + c4);
            uint4 u = { f2tf(v.x), f2tf(v.y), f2tf(v.z), f2tf(v.w) };
            *(uint4*)&Ks[r * KSTR + c4] = u;
        }
        #pragma unroll
        for (int i = 0; i < 4; i++) {
            int fi = tid + i * 128;
            int r = fi >> 3, c4 = (fi & 7) << 2;
            float4 v = *(const float4*)(Vb + (size_t)(kc * 64 + r) * Cn + c4);
            uint4 u = { f2tf(v.x), f2tf(v.y), f2tf(v.z), f2tf(v.w) };
            *(uint4*)&Vs[r * VSTR + c4] = u;
        }
        __syncthreads();

        float sc[8][4];
        #pragma unroll
        for (int nf = 0; nf < 8; nf++)
            #pragma unroll
            for (int j = 0; j < 4; j++) sc[nf][j] = 0.f;
        #pragma unroll
        for (int ks = 0; ks < 4; ks++) {
            #pragma unroll
            for (int nf = 0; nf < 8; nf++) {
                unsigned bf[2];
                bf[0] = Ks[(ks * 8 + t    ) * KSTR + nf * 8 + g];
                bf[1] = Ks[(ks * 8 + t + 4) * KSTR + nf * 8 + g];
                mma_tf32(sc[nf], qa[ks], bf);
            }
        }

        if (kc == qb) {
            int r0 = warp * 16 + g;
            #pragma unroll
            for (int nf = 0; nf < 8; nf++) {
                int c0 = nf * 8 + 2 * t;
                if (c0     > r0    ) sc[nf][0] = -1e30f;
                if (c0 + 1 > r0    ) sc[nf][1] = -1e30f;
                if (c0     > r0 + 8) sc[nf][2] = -1e30f;
                if (c0 + 1 > r0 + 8) sc[nf][3] = -1e30f;
            }
        }

        float mx0 = -1e30f, mx1 = -1e30f;
        #pragma unroll
        for (int nf = 0; nf < 8; nf++) {
            mx0 = fmaxf(mx0, fmaxf(sc[nf][0], sc[nf][1]));
            mx1 = fmaxf(mx1, fmaxf(sc[nf][2], sc[nf][3]));
        }
        #pragma unroll
        for (int o = 1; o <= 2; o <<= 1) {
            mx0 = fmaxf(mx0, __shfl_xor_sync(0xFFFFFFFFu, mx0, o));
            mx1 = fmaxf(mx1, __shfl_xor_sync(0xFFFFFFFFu, mx1, o));
        }
        float nm0 = fmaxf(m0, mx0), nm1 = fmaxf(m1, mx1);
        float al0 = __expf(m0 - nm0), al1 = __expf(m1 - nm1);

        float s0 = 0.f, s1 = 0.f;
        #pragma unroll
        for (int nf = 0; nf < 8; nf++) {
            float p0 = __expf(sc[nf][0] - nm0);
            float p1 = __expf(sc[nf][1] - nm0);
            float p2 = __expf(sc[nf][2] - nm1);
            float p3 = __expf(sc[nf][3] - nm1);
            s0 += p0 + p1; s1 += p2 + p3;
            uint2 u01 = make_uint2(f2tf(p0), f2tf(p1));
            uint2 u23 = make_uint2(f2tf(p2), f2tf(p3));
            *(uint2*)&Pw[(g    ) * PSTR + nf * 8 + 2 * t] = u01;
            *(uint2*)&Pw[(g + 8) * PSTR + nf * 8 + 2 * t] = u23;
        }
        #pragma unroll
        for (int o = 1; o <= 2; o <<= 1) {
            s0 += __shfl_xor_sync(0xFFFFFFFFu, s0, o);
            s1 += __shfl_xor_sync(0xFFFFFFFFu, s1, o);
        }
        l0 = l0 * al0 + s0;
        l1 = l1 * al1 + s1;
        m0 = nm0; m1 = nm1;

        #pragma unroll
        for (int nf = 0; nf < 4; nf++) {
            oa[nf][0] *= al0; oa[nf][1] *= al0;
            oa[nf][2] *= al1; oa[nf][3] *= al1;
        }
        __syncwarp();

        #pragma unroll
        for (int ks = 0; ks < 8; ks++) {
            unsigned pa[4];
            pa[0] = Pw[(g    ) * PSTR + ks * 8 + t    ];
            pa[1] = Pw[(g + 8) * PSTR + ks * 8 + t    ];
            pa[2] = Pw[(g    ) * PSTR + ks * 8 + t + 4];
            pa[3] = Pw[(g + 8) * PSTR + ks * 8 + t + 4];
            #pragma unroll
            for (int nf = 0; nf < 4; nf++) {
                unsigned vb[2];
                vb[0] = Vs[(ks * 8 + t    ) * VSTR + nf * 8 + g];
                vb[1] = Vs[(ks * 8 + t + 4) * VSTR + nf * 8 + g];
                mma_tf32(oa[nf], pa, vb);
            }
        }
    }

    float i0 = 1.f / l0, i1 = 1.f / l1;
    unsigned* Ob = Os + (size_t)(b * Tn + qrow) * Cn + hsoff;
    #pragma unroll
    for (int nf = 0; nf < 4; nf++) {
        int c = nf * 8 + 2 * t;
        *(uint2*)&Ob[(size_t)g       * Cn + c] =
            make_uint2(f2tf(oa[nf][0] * i0), f2tf(oa[nf][1] * i0));
        *(uint2*)&Ob[(size_t)(g + 8) * Cn + c] =
            make_uint2(f2tf(oa[nf][2] * i1), f2tf(oa[nf][3] * i1));
    }
}

// ---------------- Residual add + LayerNorm (fp32 + tf32 shadow) ----------------
__global__ __launch_bounds__(256) void add_ln_kernel(
    float* __restrict__ x, const float* __restrict__ t,
    const float* __restrict__ w, const float* __restrict__ bb,
    unsigned* __restrict__ xs)
{
    int row = blockIdx.x;
    int c = threadIdx.x;
    float v = x[(size_t)row * Cn + c];
    if (t) v += t[(size_t)row * Cn + c];

    float s = v, s2 = v * v;
    #pragma unroll
    for (int o = 16; o; o >>= 1) {
        s  += __shfl_xor_sync(0xFFFFFFFFu, s, o);
        s2 += __shfl_xor_sync(0xFFFFFFFFu, s2, o);
    }
    __shared__ float sh[16];
    int warp = c >> 5, lane = c & 31;
    if (lane == 0) { sh[warp] = s; sh[warp + 8] = s2; }
    __syncthreads();
    float sum = 0.f, sum2 = 0.f;
    #pragma unroll
    for (int i = 0; i < 8; i++) { sum += sh[i]; sum2 += sh[i + 8]; }

    float mean = sum * (1.f / Cn);
    float var  = sum2 * (1.f / Cn) - mean * mean;
    float r = rsqrtf(var + EPSF);
    float out = (v - mean) * r * w[c] + bb[c];
    x[(size_t)row * Cn + c] = out;
    xs[(size_t)row * Cn + c] = f2tf(out);
}

// ---------------- Loss ----------------
__global__ __launch_bounds__(256) void loss_row_kernel(
    const float* __restrict__ logits, const int* __restrict__ target,
    float* __restrict__ nll)
{
    int gwarp = (blockIdx.x * blockDim.x + threadIdx.x) >> 5;
    int lane = threadIdx.x & 31;
    if (gwarp >= NROWS) return;
    const float* lg = logits + (size_t)gwarp * Vn;
    float v0 = lg[lane], v1 = lg[lane + 32], v2 = lg[lane + 64];
    float mx = fmaxf(v0, fmaxf(v1, v2));
    #pragma unroll
    for (int o = 16; o; o >>= 1) mx = fmaxf(mx, __shfl_xor_sync(0xFFFFFFFFu, mx, o));
    float s = __expf(v0 - mx) + __expf(v1 - mx) + __expf(v2 - mx);
    #pragma unroll
    for (int o = 16; o; o >>= 1) s += __shfl_xor_sync(0xFFFFFFFFu, s, o);
    if (lane == 0) {
        float lse = mx + logf(s);
        nll[gwarp] = lse - lg[target[gwarp]];
    }
}

__global__ __launch_bounds__(256) void loss_reduce_kernel(
    const float* __restrict__ nll, float* __restrict__ out)
{
    __shared__ float sh[256];
    float s = 0.f;
    for (int i = threadIdx.x; i < NROWS; i += 256) s += nll[i];
    sh[threadIdx.x] = s;
    __syncthreads();
    for (int st = 128; st; st >>= 1) {
        if (threadIdx.x < st) sh[threadIdx.x] += sh[threadIdx.x + st];
        __syncthreads();
    }
    if (threadIdx.x == 0) out[0] = sh[0] * (1.f / NROWS);
}

// ---------------- Host-side launch sequence (graph-capturable) ----------------
extern "C" void kernel_launch(void* const* d_in, const int* in_sizes, int n_in,
                              void* d_out, int out_size) {
    const int*   idx    = (const int*)  d_in[0];
    const int*   target = (const int*)  d_in[1];
    const float* tok    = (const float*)d_in[2];
    const float* pos    = (const float*)d_in[3];
    const float* Wq     = (const float*)d_in[4];
    const float* Wk     = (const float*)d_in[5];
    const float* Wv     = (const float*)d_in[6];
    const float* Wo     = (const float*)d_in[7];
    const float* bo     = (const float*)d_in[8];
    const float* W1     = (const float*)d_in[9];
    const float* b1     = (const float*)d_in[10];
    const float* W2     = (const float*)d_in[11];
    const float* b2     = (const float*)d_in[12];
    const float* ln1w   = (const float*)d_in[13];
    const float* ln1b   = (const float*)d_in[14];
    const float* ln2w   = (const float*)d_in[15];
    const float* ln2b   = (const float*)d_in[16];
    const float* lnfw   = (const float*)d_in[17];
    const float* lnfb   = (const float*)d_in[18];
    const float* Wlm    = (const float*)d_in[19];
    const float* blm    = (const float*)d_in[20];

    float* logits = (float*)d_out;

    float* s = nullptr;
    cudaGetSymbolAddress((void**)&s, g_scratch);
    unsigned* sh = nullptr;
    cudaGetSymbolAddress((void**)&sh, g_shadow);
    unsigned* wt = nullptr;
    cudaGetSymbolAddress((void**)&wt, g_wt);

    float* x   = s;
    float* ba  = s + 1 * (size_t)NROWS * Cn;
    float* bb  = s + 2 * (size_t)NROWS * Cn;   // K^T fp32
    float* bc  = s + 3 * (size_t)NROWS * Cn;
    float* nll = s + 4 * (size_t)NROWS * Cn;
    unsigned* xs  = sh;
    unsigned* bds = sh + 1 * (size_t)NROWS * Cn;
    unsigned* bbs = sh + 2 * (size_t)NROWS * Cn;

    cudaFuncSetAttribute(gemm_tc_kernel,
                         cudaFuncAttributeMaxDynamicSharedMemorySize, GSMEM);
    cudaFuncSetAttribute(gemm_qkv_kernel,
                         cudaFuncAttributeMaxDynamicSharedMemorySize, GSMEM);

    dim3 gemmGridC(Cn / 64, NROWS / 128);          // (4, 128)
    dim3 gemmGridV((Vn + 63) / 64, NROWS / 128);   // (2, 128)
    dim3 qkvGrid(Cn / 64, NROWS / 128, 3);
    dim3 attnGrid(4, Hn, Bn);

    // weight pre-pass: tf32 transposed copies
    wt_kernel<<<dim3(8, 8, 37), dim3(32, 8)>>>(Wq, Wk, Wv, Wo, W1, W2, Wlm, wt);

    embed_kernel<<<NROWS, 256>>>(idx, tok, pos, x, xs);

    for (int l = 0; l < Ln; l++) {
        const unsigned* wtl = wt + (size_t)l * 6 * CC;

        gemm_qkv_kernel<<<qkvGrid, 256, GSMEM>>>(xs, wtl, ba, bb, bc);

        attn_tc_kernel<<<attnGrid, 128>>>(ba, bb, bc, bds);

        gemm_tc_kernel<<<gemmGridC, 256, GSMEM>>>(bds, wtl + 3 * CC,
            bo + (size_t)l * Cn, ba, nullptr, Cn, 0, 0);
        add_ln_kernel<<<NROWS, 256>>>(x, ba,
            ln1w + (size_t)l * Cn, ln1b + (size_t)l * Cn, xs);

        gemm_tc_kernel<<<gemmGridC, 256, GSMEM>>>(xs, wtl + 4 * CC,
            b1 + (size_t)l * Cn, nullptr, bbs, Cn, 1, 0);
        gemm_tc_kernel<<<gemmGridC, 256, GSMEM>>>(bbs, wtl + 5 * CC,
            b2 + (size_t)l * Cn, bc, nullptr, Cn, 0, 0);
        add_ln_kernel<<<NROWS, 256>>>(x, bc,
            ln2w + (size_t)l * Cn, ln2b + (size_t)l * Cn, xs);
    }

    add_ln_kernel<<<NROWS, 256>>>(x, nullptr, lnfw, lnfb, xs);
    gemm_tc_kernel<<<gemmGridV, 256, GSMEM>>>(xs, wt + 36 * CC, blm,
        logits, nullptr, Vn, 0, 0);

    if (out_size > NROWS * Vn) {
        loss_row_kernel<<<NROWS / 8, 256>>>(logits, target, nll);
        loss_reduce_kernel<<<1, 256>>>(nll, logits + (size_t)NROWS * Vn);
    }
}

// round 15
// speedup vs baseline: 1.2427x; 1.0260x over previous
#include <cuda_runtime.h>
#include <cuda_bf16.h>

// ---------------- Problem constants ----------------
#define Bn    64
#define Tn    256
#define Cn    256
#define Hn    8
#define HSn   32         // head size
#define Ln    6
#define Vn    96
#define NROWS (Bn*Tn)    // 16384
#define CC    (Cn*Cn)    // 65536
#define EPSF  1e-5f
#define KK    256

// ---------------- Scratch (static device memory; no allocation) ----------------
__device__ float    g_scratch[3 * NROWS * Cn + NROWS];   // x, ba, bc, nll
__device__ unsigned g_shadow [6 * NROWS * Cn];            // xs, qs, ks, vt, bds, bbs (tf32)
__device__ unsigned g_wt     [36 * CC + 128 * 256];       // tf32 W^T, lm padded

// ---------------- helpers ----------------
__device__ __forceinline__ unsigned f2tf(float f) {
    unsigned u;
    asm("cvt.rna.tf32.f32 %0, %1;" : "=r"(u) : "f"(f));
    return u;
}
__device__ __forceinline__ void mma_tf32(float* d, const unsigned* a, const unsigned* b) {
    asm volatile("mma.sync.aligned.m16n8k8.row.col.f32.tf32.tf32.f32 "
        "{%0,%1,%2,%3}, {%4,%5,%6,%7}, {%8,%9}, {%0,%1,%2,%3};"
        : "+f"(d[0]), "+f"(d[1]), "+f"(d[2]), "+f"(d[3])
        : "r"(a[0]), "r"(a[1]), "r"(a[2]), "r"(a[3]), "r"(b[0]), "r"(b[1]));
}
__device__ __forceinline__ void ldsm4(unsigned* r, unsigned addr) {
    asm volatile("ldmatrix.sync.aligned.m8n8.x4.shared.b16 {%0,%1,%2,%3}, [%4];"
        : "=r"(r[0]), "=r"(r[1]), "=r"(r[2]), "=r"(r[3]) : "r"(addr));
}
__device__ __forceinline__ void cp16(unsigned dst, const void* src) {
    asm volatile("cp.async.cg.shared.global [%0], [%1], 16;" :: "r"(dst), "l"(src) : "memory");
}
__device__ __forceinline__ unsigned smem_u32(const void* p) {
    return (unsigned)__cvta_generic_to_shared(p);
}

// ---------------- Weight pre-pass: Wt[n][k] = tf32(W[k][n]) ----------------
__global__ void wt_kernel(const float* __restrict__ Wq, const float* __restrict__ Wk,
                          const float* __restrict__ Wv, const float* __restrict__ Wo,
                          const float* __restrict__ W1, const float* __restrict__ W2,
                          const float* __restrict__ Wlm, unsigned* __restrict__ wt)
{
    __shared__ float tl[32][33];
    int id = blockIdx.z;
    int kt = blockIdx.x * 32, nt = blockIdx.y * 32;
    const float* src;
    unsigned* dst;
    int nsrc;
    if (id < 36) {
        int l = id / 6, m = id % 6;
        const float* bases[6] = {Wq, Wk, Wv, Wo, W1, W2};
        src = bases[m] + (size_t)l * CC;
        dst = wt + (size_t)id * CC;
        nsrc = 256;
    } else {
        if (nt >= 128) return;
        src = Wlm;
        dst = wt + 36 * CC;
        nsrc = 96;
    }
    int tx = threadIdx.x, ty = threadIdx.y;
    #pragma unroll
    for (int i = 0; i < 4; i++) {
        int k = kt + ty * 4 + i;
        int n = nt + tx;
        tl[ty * 4 + i][tx] = (n < nsrc) ? src[(size_t)k * nsrc + n] : 0.f;
    }
    __syncthreads();
    #pragma unroll
    for (int i = 0; i < 4; i++)
        dst[(size_t)(nt + ty * 4 + i) * 256 + kt + tx] = f2tf(tl[tx][ty * 4 + i]);
}

// ---------------- Embedding (fp32 + tf32 shadow) ----------------
__global__ void embed_kernel(const int* __restrict__ idx,
                             const float* __restrict__ tok,
                             const float* __restrict__ pos,
                             float* __restrict__ x, unsigned* __restrict__ xs) {
    int row = blockIdx.x;
    int c = threadIdx.x;
    int token = idx[row];
    float v = tok[token * Cn + c] + pos[(row & (Tn - 1)) * Cn + c];
    x[row * Cn + c] = v;
    xs[row * Cn + c] = f2tf(v);
}

// ---------------- Tensor-core tf32 GEMM: cp.async + ldmatrix ----------------
// CTA 128x64, BK=32, 8 warps (4M x 2N), warp tile 32x32, double buffered.
#define SSTR 36
#define ABUF_B (128*SSTR*4)
#define BBUF_B (64*SSTR*4)
#define GSMEM  (2*ABUF_B + 2*BBUF_B)   // 55296 B

__device__ __forceinline__ void gemm_core(
    const unsigned* __restrict__ A, const unsigned* __restrict__ Wt,
    const float* __restrict__ bias, float* __restrict__ Cout,
    unsigned* __restrict__ shadow, float sscale,
    int Nd, int relu, int transT, char* smem)
{
    const unsigned sbase = smem_u32(smem);
    const int tid = threadIdx.x;
    const int lane = tid & 31, warp = tid >> 5;
    const int g = lane >> 2, t = lane & 3;
    const int wm = (warp & 3) * 32, wn = (warp >> 2) * 32;
    const int aRowBase = blockIdx.y * 128;
    const int bColBase = blockIdx.x * 64;

    float acc[2][4][4] = {};

    const unsigned* aSrc = A  + (size_t)(aRowBase + (tid >> 3)) * 256 + (tid & 7) * 4;
    const unsigned* bSrc = Wt + (size_t)(bColBase + (tid >> 3)) * 256 + (tid & 7) * 4;
    const unsigned aDst = sbase + (tid >> 3) * (SSTR * 4) + (tid & 7) * 16;
    const unsigned bDst = sbase + 2 * ABUF_B + (tid >> 3) * (SSTR * 4) + (tid & 7) * 16;

    unsigned aAddr0, aAddr1, bAddr0, bAddr1;
    {
        int l15 = lane & 15, lh = lane >> 4;
        aAddr0 = sbase + ((wm + l15) * SSTR + lh * 4) * 4;
        aAddr1 = aAddr0 + 16 * SSTR * 4;
        int brow = wn + ((lane >> 4) << 3) + (lane & 7);
        int bk = ((lane >> 3) & 1) * 4;
        bAddr0 = sbase + 2 * ABUF_B + (brow * SSTR + bk) * 4;
        bAddr1 = bAddr0 + 16 * SSTR * 4;
    }

    #pragma unroll
    for (int i = 0; i < 4; i++) cp16(aDst + i * 32 * SSTR * 4, aSrc + i * 32 * 256);
    #pragma unroll
    for (int i = 0; i < 2; i++) cp16(bDst + i * 32 * SSTR * 4, bSrc + i * 32 * 256);
    asm volatile("cp.async.commit_group;" ::: "memory");

    for (int kt = 0; kt < 8; kt++) {
        int cur = kt & 1;
        asm volatile("cp.async.wait_group 0;" ::: "memory");
        __syncthreads();

        if (kt < 7) {
            int koff = (kt + 1) * 32;
            unsigned ao = (1 - cur) * ABUF_B, bo = (1 - cur) * BBUF_B;
            #pragma unroll
            for (int i = 0; i < 4; i++)
                cp16(aDst + ao + i * 32 * SSTR * 4, aSrc + i * 32 * 256 + koff);
            #pragma unroll
            for (int i = 0; i < 2; i++)
                cp16(bDst + bo + i * 32 * SSTR * 4, bSrc + i * 32 * 256 + koff);
            asm volatile("cp.async.commit_group;" ::: "memory");
        }

        unsigned aob = cur * ABUF_B, bob = cur * BBUF_B;
        #pragma unroll
        for (int ks = 0; ks < 4; ks++) {
            unsigned a0[4], a1[4], b0[4], b1[4];
            ldsm4(a0, aAddr0 + aob + ks * 32);
            ldsm4(a1, aAddr1 + aob + ks * 32);
            ldsm4(b0, bAddr0 + bob + ks * 32);
            ldsm4(b1, bAddr1 + bob + ks * 32);
            mma_tf32(acc[0][0], a0, b0 + 0);
            mma_tf32(acc[0][1], a0, b0 + 2);
            mma_tf32(acc[0][2], a0, b1 + 0);
            mma_tf32(acc[0][3], a0, b1 + 2);
            mma_tf32(acc[1][0], a1, b0 + 0);
            mma_tf32(acc[1][1], a1, b0 + 2);
            mma_tf32(acc[1][2], a1, b1 + 0);
            mma_tf32(acc[1][3], a1, b1 + 2);
        }
    }

    if (!transT) {
        #pragma unroll
        for (int i = 0; i < 2; i++) {
            #pragma unroll
            for (int j = 0; j < 4; j++) {
                int col = bColBase + wn + j * 8 + t * 2;
                if (col >= Nd) continue;
                float bx = 0.f, by = 0.f;
                if (bias) { bx = bias[col]; by = bias[col + 1]; }
                int r0 = aRowBase + wm + i * 16 + g;
                float v0 = acc[i][j][0] + bx, v1 = acc[i][j][1] + by;
                float v2 = acc[i][j][2] + bx, v3 = acc[i][j][3] + by;
                if (relu) {
                    v0 = fmaxf(v0, 0.f); v1 = fmaxf(v1, 0.f);
                    v2 = fmaxf(v2, 0.f); v3 = fmaxf(v3, 0.f);
                }
                if (Cout) {
                    *(float2*)&Cout[(size_t)r0 * Nd + col]       = make_float2(v0, v1);
                    *(float2*)&Cout[(size_t)(r0 + 8) * Nd + col] = make_float2(v2, v3);
                }
                if (shadow) {
                    *(uint2*)&shadow[(size_t)r0 * Nd + col] =
                        make_uint2(f2tf(v0 * sscale), f2tf(v1 * sscale));
                    *(uint2*)&shadow[(size_t)(r0 + 8) * Nd + col] =
                        make_uint2(f2tf(v2 * sscale), f2tf(v3 * sscale));
                }
            }
        }
    } else {
        // transposed epilogue: shadow[b][c][t] tf32, via per-warp smem patch
        __syncthreads();
        float* patch = (float*)smem + warp * 1056;   // 32 x 32, stride 33
        #pragma unroll
        for (int i = 0; i < 2; i++) {
            #pragma unroll
            for (int j = 0; j < 4; j++) {
                int c0 = j * 8 + t * 2;
                int r0 = i * 16 + g;
                patch[(c0    ) * 33 + r0    ] = acc[i][j][0];
                patch[(c0 + 1) * 33 + r0    ] = acc[i][j][1];
                patch[(c0    ) * 33 + r0 + 8] = acc[i][j][2];
                patch[(c0 + 1) * 33 + r0 + 8] = acc[i][j][3];
            }
        }
        __syncwarp();
        int rowG = aRowBase + wm;
        int bIdx = rowG >> 8;
        int tg = (lane & 7) * 4;
        int chi = lane >> 3;
        int tBase = (rowG & 255) + tg;
        #pragma unroll
        for (int jj = 0; jj < 8; jj++) {
            int c = jj * 4 + chi;
            uint4 v;
            v.x = f2tf(patch[c * 33 + tg + 0]);
            v.y = f2tf(patch[c * 33 + tg + 1]);
            v.z = f2tf(patch[c * 33 + tg + 2]);
            v.w = f2tf(patch[c * 33 + tg + 3]);
            *(uint4*)&shadow[(size_t)bIdx * (Cn * Tn) +
                             (size_t)(bColBase + wn + c) * Tn + tBase] = v;
        }
    }
}

__global__ __launch_bounds__(256, 3) void gemm_tc_kernel(
    const unsigned* __restrict__ A, const unsigned* __restrict__ Wt,
    const float* __restrict__ bias, float* __restrict__ Cout,
    unsigned* __restrict__ shadow, float sscale, int Nd, int relu)
{
    extern __shared__ char gsm[];
    gemm_core(A, Wt, bias, Cout, shadow, sscale, Nd, relu, 0, gsm);
}

// fused Q/K/V: all outputs tf32. z=0: Q (scaled 1/16), z=1: K, z=2: V transposed
__global__ __launch_bounds__(256, 3) void gemm_qkv_kernel(
    const unsigned* __restrict__ A, const unsigned* __restrict__ wtBase,
    unsigned* __restrict__ oq, unsigned* __restrict__ ok, unsigned* __restrict__ ovt)
{
    extern __shared__ char gsm[];
    int z = blockIdx.z;
    const unsigned* Wt = wtBase + (size_t)z * CC;
    unsigned* o = (z == 0) ? oq : (z == 1) ? ok : ovt;
    float scl = (z == 0) ? 0.0625f : 1.0f;
    gemm_core(A, Wt, nullptr, nullptr, o, scl, Cn, 0, (z == 2) ? 1 : 0, gsm);
}

// ---------------- Tensor-core flash attention (cp.async + ldmatrix) ----------------
// Grid (4, Hn, Bn), 128 threads (4 warps), warp = 16 query rows, 64-key chunks.
// Ks smem [key64][hs32] (B-op for QK), Vs smem [hs32][key64] (B-op for PV, from VT),
// P smem row-major [q16][key64] (A-op for PV).
#define AKSTR 36
#define AVSTR 68
#define APSTR 68
#define KBUF  (64*AKSTR)    // u32
#define VBUF  (32*AVSTR)    // u32
#define ASMEM ((2*KBUF + 2*VBUF + 4*16*APSTR) * 4)   // 53248 B

__global__ __launch_bounds__(128, 4) void attn_tc_kernel(
    const unsigned* __restrict__ Qs,   // tf32 [B*T, C], pre-scaled
    const unsigned* __restrict__ Kg,   // tf32 [B*T, C]
    const unsigned* __restrict__ VTg,  // tf32 [B][C][T]
    unsigned* __restrict__ Os)         // tf32 [B*T, C]
{
    extern __shared__ unsigned dsm[];
    unsigned* sPw = dsm + 2 * KBUF + 2 * VBUF;

    int qb = 3 - blockIdx.x;
    int h  = blockIdx.y;
    int b  = blockIdx.z;
    int tid = threadIdx.x;
    int warp = tid >> 5, lane = tid & 31;
    int g = lane >> 2, t = lane & 3;
    int hsoff = h * HSn;
    int qrow = qb * 64 + warp * 16;

    // Q fragments straight from tf32 global
    unsigned qa[4][4];
    {
        const unsigned* Qb = Qs + (size_t)(b * Tn + qrow) * Cn + hsoff;
        #pragma unroll
        for (int ks = 0; ks < 4; ks++) {
            qa[ks][0] = Qb[(size_t)g       * Cn + ks * 8 + t];
            qa[ks][1] = Qb[(size_t)(g + 8) * Cn + ks * 8 + t];
            qa[ks][2] = Qb[(size_t)g       * Cn + ks * 8 + t + 4];
            qa[ks][3] = Qb[(size_t)(g + 8) * Cn + ks * 8 + t + 4];
        }
    }

    const unsigned sK0 = smem_u32(dsm);
    const unsigned sV0 = sK0 + 2 * KBUF * 4;
    const unsigned sP  = sV0 + 2 * VBUF * 4 + warp * (16 * APSTR * 4);
    unsigned* Pw = sPw + warp * (16 * APSTR);

    // staging (cp.async) addresses
    const unsigned* kSrc = Kg + (size_t)(b * Tn + (tid >> 3)) * Cn + hsoff + (tid & 7) * 4;
    const unsigned  kDst = sK0 + (tid >> 3) * (AKSTR * 4) + (tid & 7) * 16;
    const unsigned* vSrc = VTg + ((size_t)b * Cn + hsoff + (tid >> 4)) * Tn + (tid & 15) * 4;
    const unsigned  vDst = sV0 + (tid >> 4) * (AVSTR * 4) + (tid & 15) * 16;

    // ldmatrix addresses
    const unsigned kfAddr = sK0 + ((((lane >> 4) << 3) + (lane & 7)) * AKSTR + ((lane >> 3) & 1) * 4) * 4;
    const unsigned vfAddr = sV0 + ((((lane >> 4) << 3) + (lane & 7)) * AVSTR + ((lane >> 3) & 1) * 4) * 4;
    const unsigned pfAddr = sP + ((lane & 15) * APSTR + (lane >> 4) * 4) * 4;

    float oa[4][4] = {};
    float m0 = -1e30f, m1 = -1e30f, l0 = 0.f, l1 = 0.f;

    // prologue: stage chunk 0 -> buffer 0
    #pragma unroll
    for (int i = 0; i < 4; i++) cp16(kDst + i * 16 * AKSTR * 4, kSrc + (size_t)i * 16 * Cn);
    #pragma unroll
    for (int i = 0; i < 4; i++) cp16(vDst + i * 8 * AVSTR * 4, vSrc + (size_t)i * 8 * Tn);
    asm volatile("cp.async.commit_group;" ::: "memory");

    for (int kc = 0; kc <= qb; kc++) {
        int cur = kc & 1;
        if (kc < qb) {
            int nxt = 1 - cur;
            int koff = (kc + 1) * 64;
            #pragma unroll
            for (int i = 0; i < 4; i++)
                cp16(kDst + nxt * KBUF * 4 + i * 16 * AKSTR * 4,
                     kSrc + (size_t)(koff + i * 16) * Cn);
            #pragma unroll
            for (int i = 0; i < 4; i++)
                cp16(vDst + nxt * VBUF * 4 + i * 8 * AVSTR * 4,
                     vSrc + koff + (size_t)i * 8 * Tn);
            asm volatile("cp.async.commit_group;" ::: "memory");
            asm volatile("cp.async.wait_group 1;" ::: "memory");
        } else {
            asm volatile("cp.async.wait_group 0;" ::: "memory");
        }
        __syncthreads();

        unsigned ko = cur * KBUF * 4, vo = cur * VBUF * 4;

        // S = Q @ K^T : [16 x 64]
        float sc[8][4];
        #pragma unroll
        for (int nf = 0; nf < 8; nf++)
            #pragma unroll
            for (int j = 0; j < 4; j++) sc[nf][j] = 0.f;
        #pragma unroll
        for (int ks = 0; ks < 4; ks++) {
            #pragma unroll
            for (int np = 0; np < 4; np++) {
                unsigned bf[4];
                ldsm4(bf, kfAddr + ko + np * (16 * AKSTR * 4) + ks * 32);
                mma_tf32(sc[2 * np    ], qa[ks], bf + 0);
                mma_tf32(sc[2 * np + 1], qa[ks], bf + 2);
            }
        }

        // causal mask on diagonal chunk
        if (kc == qb) {
            int r0 = warp * 16 + g;
            #pragma unroll
            for (int nf = 0; nf < 8; nf++) {
                int c0 = nf * 8 + 2 * t;
                if (c0     > r0    ) sc[nf][0] = -1e30f;
                if (c0 + 1 > r0    ) sc[nf][1] = -1e30f;
                if (c0     > r0 + 8) sc[nf][2] = -1e30f;
                if (c0 + 1 > r0 + 8) sc[nf][3] = -1e30f;
            }
        }

        // online softmax
        float mx0 = -1e30f, mx1 = -1e30f;
        #pragma unroll
        for (int nf = 0; nf < 8; nf++) {
            mx0 = fmaxf(mx0, fmaxf(sc[nf][0], sc[nf][1]));
            mx1 = fmaxf(mx1, fmaxf(sc[nf][2], sc[nf][3]));
        }
        #pragma unroll
        for (int o = 1; o <= 2; o <<= 1) {
            mx0 = fmaxf(mx0, __shfl_xor_sync(0xFFFFFFFFu, mx0, o));
            mx1 = fmaxf(mx1, __shfl_xor_sync(0xFFFFFFFFu, mx1, o));
        }
        float nm0 = fmaxf(m0, mx0), nm1 = fmaxf(m1, mx1);
        float al0 = __expf(m0 - nm0), al1 = __expf(m1 - nm1);

        float s0 = 0.f, s1 = 0.f;
        #pragma unroll
        for (int nf = 0; nf < 8; nf++) {
            float p0 = __expf(sc[nf][0] - nm0);
            float p1 = __expf(sc[nf][1] - nm0);
            float p2 = __expf(sc[nf][2] - nm1);
            float p3 = __expf(sc[nf][3] - nm1);
            s0 += p0 + p1; s1 += p2 + p3;
            *(uint2*)&Pw[(g    ) * APSTR + nf * 8 + 2 * t] = make_uint2(f2tf(p0), f2tf(p1));
            *(uint2*)&Pw[(g + 8) * APSTR + nf * 8 + 2 * t] = make_uint2(f2tf(p2), f2tf(p3));
        }
        #pragma unroll
        for (int o = 1; o <= 2; o <<= 1) {
            s0 += __shfl_xor_sync(0xFFFFFFFFu, s0, o);
            s1 += __shfl_xor_sync(0xFFFFFFFFu, s1, o);
        }
        l0 = l0 * al0 + s0;
        l1 = l1 * al1 + s1;
        m0 = nm0; m1 = nm1;

        #pragma unroll
        for (int nf = 0; nf < 4; nf++) {
            oa[nf][0] *= al0; oa[nf][1] *= al0;
            oa[nf][2] *= al1; oa[nf][3] *= al1;
        }
        __syncwarp();

        // out += P @ V : [16 x 64] @ [64 x 32]
        #pragma unroll
        for (int ks = 0; ks < 8; ks++) {
            unsigned pa[4], vb0[4], vb1[4];
            ldsm4(pa,  pfAddr + ks * 32);
            ldsm4(vb0, vfAddr + vo + ks * 32);
            ldsm4(vb1, vfAddr + vo + 16 * AVSTR * 4 + ks * 32);
            mma_tf32(oa[0], pa, vb0 + 0);
            mma_tf32(oa[1], pa, vb0 + 2);
            mma_tf32(oa[2], pa, vb1 + 0);
            mma_tf32(oa[3], pa, vb1 + 2);
        }
        __syncthreads();
    }

    float i0 = 1.f / l0, i1 = 1.f / l1;
    unsigned* Ob = Os + (size_t)(b * Tn + qrow) * Cn + hsoff;
    #pragma unroll
    for (int nf = 0; nf < 4; nf++) {
        int c = nf * 8 + 2 * t;
        *(uint2*)&Ob[(size_t)g       * Cn + c] =
            make_uint2(f2tf(oa[nf][0] * i0), f2tf(oa[nf][1] * i0));
        *(uint2*)&Ob[(size_t)(g + 8) * Cn + c] =
            make_uint2(f2tf(oa[nf][2] * i1), f2tf(oa[nf][3] * i1));
    }
}

// ---------------- Residual add + LayerNorm (fp32 + tf32 shadow) ----------------
__global__ __launch_bounds__(256) void add_ln_kernel(
    float* __restrict__ x, const float* __restrict__ t,
    const float* __restrict__ w, const float* __restrict__ bb,
    unsigned* __restrict__ xs)
{
    int row = blockIdx.x;
    int c = threadIdx.x;
    float v = x[(size_t)row * Cn + c];
    if (t) v += t[(size_t)row * Cn + c];

    float s = v, s2 = v * v;
    #pragma unroll
    for (int o = 16; o; o >>= 1) {
        s  += __shfl_xor_sync(0xFFFFFFFFu, s, o);
        s2 += __shfl_xor_sync(0xFFFFFFFFu, s2, o);
    }
    __shared__ float sh[16];
    int warp = c >> 5, lane = c & 31;
    if (lane == 0) { sh[warp] = s; sh[warp + 8] = s2; }
    __syncthreads();
    float sum = 0.f, sum2 = 0.f;
    #pragma unroll
    for (int i = 0; i < 8; i++) { sum += sh[i]; sum2 += sh[i + 8]; }

    float mean = sum * (1.f / Cn);
    float var  = sum2 * (1.f / Cn) - mean * mean;
    float r = rsqrtf(var + EPSF);
    float out = (v - mean) * r * w[c] + bb[c];
    x[(size_t)row * Cn + c] = out;
    xs[(size_t)row * Cn + c] = f2tf(out);
}

// ---------------- Loss ----------------
__global__ __launch_bounds__(256) void loss_row_kernel(
    const float* __restrict__ logits, const int* __restrict__ target,
    float* __restrict__ nll)
{
    int gwarp = (blockIdx.x * blockDim.x + threadIdx.x) >> 5;
    int lane = threadIdx.x & 31;
    if (gwarp >= NROWS) return;
    const float* lg = logits + (size_t)gwarp * Vn;
    float v0 = lg[lane], v1 = lg[lane + 32], v2 = lg[lane + 64];
    float mx = fmaxf(v0, fmaxf(v1, v2));
    #pragma unroll
    for (int o = 16; o; o >>= 1) mx = fmaxf(mx, __shfl_xor_sync(0xFFFFFFFFu, mx, o));
    float s = __expf(v0 - mx) + __expf(v1 - mx) + __expf(v2 - mx);
    #pragma unroll
    for (int o = 16; o; o >>= 1) s += __shfl_xor_sync(0xFFFFFFFFu, s, o);
    if (lane == 0) {
        float lse = mx + logf(s);
        nll[gwarp] = lse - lg[target[gwarp]];
    }
}

__global__ __launch_bounds__(256) void loss_reduce_kernel(
    const float* __restrict__ nll, float* __restrict__ out)
{
    __shared__ float sh[256];
    float s = 0.f;
    for (int i = threadIdx.x; i < NROWS; i += 256) s += nll[i];
    sh[threadIdx.x] = s;
    __syncthreads();
    for (int st = 128; st; st >>= 1) {
        if (threadIdx.x < st) sh[threadIdx.x] += sh[threadIdx.x + st];
        __syncthreads();
    }
    if (threadIdx.x == 0) out[0] = sh[0] * (1.f / NROWS);
}

// ---------------- Host-side launch sequence (graph-capturable) ----------------
extern "C" void kernel_launch(void* const* d_in, const int* in_sizes, int n_in,
                              void* d_out, int out_size) {
    const int*   idx    = (const int*)  d_in[0];
    const int*   target = (const int*)  d_in[1];
    const float* tok    = (const float*)d_in[2];
    const float* pos    = (const float*)d_in[3];
    const float* Wq     = (const float*)d_in[4];
    const float* Wk     = (const float*)d_in[5];
    const float* Wv     = (const float*)d_in[6];
    const float* Wo     = (const float*)d_in[7];
    const float* bo     = (const float*)d_in[8];
    const float* W1     = (const float*)d_in[9];
    const float* b1     = (const float*)d_in[10];
    const float* W2     = (const float*)d_in[11];
    const float* b2     = (const float*)d_in[12];
    const float* ln1w   = (const float*)d_in[13];
    const float* ln1b   = (const float*)d_in[14];
    const float* ln2w   = (const float*)d_in[15];
    const float* ln2b   = (const float*)d_in[16];
    const float* lnfw   = (const float*)d_in[17];
    const float* lnfb   = (const float*)d_in[18];
    const float* Wlm    = (const float*)d_in[19];
    const float* blm    = (const float*)d_in[20];

    float* logits = (float*)d_out;

    float* s = nullptr;
    cudaGetSymbolAddress((void**)&s, g_scratch);
    unsigned* sh = nullptr;
    cudaGetSymbolAddress((void**)&sh, g_shadow);
    unsigned* wt = nullptr;
    cudaGetSymbolAddress((void**)&wt, g_wt);

    float* x   = s;
    float* ba  = s + 1 * (size_t)NROWS * Cn;
    float* bc  = s + 2 * (size_t)NROWS * Cn;
    float* nll = s + 3 * (size_t)NROWS * Cn;
    unsigned* xs  = sh;
    unsigned* qs  = sh + 1 * (size_t)NROWS * Cn;
    unsigned* ksb = sh + 2 * (size_t)NROWS * Cn;
    unsigned* vts = sh + 3 * (size_t)NROWS * Cn;
    unsigned* bds = sh + 4 * (size_t)NROWS * Cn;
    unsigned* bbs = sh + 5 * (size_t)NROWS * Cn;

    cudaFuncSetAttribute(gemm_tc_kernel,
                         cudaFuncAttributeMaxDynamicSharedMemorySize, GSMEM);
    cudaFuncSetAttribute(gemm_qkv_kernel,
                         cudaFuncAttributeMaxDynamicSharedMemorySize, GSMEM);
    cudaFuncSetAttribute(attn_tc_kernel,
                         cudaFuncAttributeMaxDynamicSharedMemorySize, ASMEM);

    dim3 gemmGridC(Cn / 64, NROWS / 128);          // (4, 128)
    dim3 gemmGridV((Vn + 63) / 64, NROWS / 128);   // (2, 128)
    dim3 qkvGrid(Cn / 64, NROWS / 128, 3);
    dim3 attnGrid(4, Hn, Bn);

    wt_kernel<<<dim3(8, 8, 37), dim3(32, 8)>>>(Wq, Wk, Wv, Wo, W1, W2, Wlm, wt);
    embed_kernel<<<NROWS, 256>>>(idx, tok, pos, x, xs);

    for (int l = 0; l < Ln; l++) {
        const unsigned* wtl = wt + (size_t)l * 6 * CC;

        gemm_qkv_kernel<<<qkvGrid, 256, GSMEM>>>(xs, wtl, qs, ksb, vts);

        attn_tc_kernel<<<attnGrid, 128, ASMEM>>>(qs, ksb, vts, bds);

        gemm_tc_kernel<<<gemmGridC, 256, GSMEM>>>(bds, wtl + 3 * CC,
            bo + (size_t)l * Cn, ba, nullptr, 1.f, Cn, 0);
        add_ln_kernel<<<NROWS, 256>>>(x, ba,
            ln1w + (size_t)l * Cn, ln1b + (size_t)l * Cn, xs);

        gemm_tc_kernel<<<gemmGridC, 256, GSMEM>>>(xs, wtl + 4 * CC,
            b1 + (size_t)l * Cn, nullptr, bbs, 1.f, Cn, 1);
        gemm_tc_kernel<<<gemmGridC, 256, GSMEM>>>(bbs, wtl + 5 * CC,
            b2 + (size_t)l * Cn, bc, nullptr, 1.f, Cn, 0);
        add_ln_kernel<<<NROWS, 256>>>(x, bc,
            ln2w + (size_t)l * Cn, ln2b + (size_t)l * Cn, xs);
    }

    add_ln_kernel<<<NROWS, 256>>>(x, nullptr, lnfw, lnfb, xs);
    gemm_tc_kernel<<<gemmGridV, 256, GSMEM>>>(xs, wt + 36 * CC, blm,
        logits, nullptr, 1.f, Vn, 0);

    if (out_size > NROWS * Vn) {
        loss_row_kernel<<<NROWS / 8, 256>>>(logits, target, nll);
        loss_reduce_kernel<<<1, 256>>>(nll, logits + (size_t)NROWS * Vn);
    }
}

// round 16
// speedup vs baseline: 1.4302x; 1.1509x over previous
#include <cuda_runtime.h>
#include <cuda_bf16.h>

// ---------------- Problem constants ----------------
#define Bn    64
#define Tn    256
#define Cn    256
#define Hn    8
#define HSn   32
#define Ln    6
#define Vn    96
#define NROWS (Bn*Tn)
#define CC    (Cn*Cn)
#define EPSF  1e-5f
#define KK    256

// ---------------- Scratch ----------------
__device__ float    g_scratch[NROWS * Cn + NROWS];        // x, nll
__device__ unsigned g_shadow [6 * NROWS * Cn];            // xs, qs, ks, vt, bds, bbs
__device__ unsigned g_wt     [36 * CC + 128 * 256];       // tf32 W^T

// ---------------- helpers ----------------
__device__ __forceinline__ unsigned f2tf(float f) {
    unsigned u;
    asm("cvt.rna.tf32.f32 %0, %1;" : "=r"(u) : "f"(f));
    return u;
}
__device__ __forceinline__ void mma_tf32(float* d, const unsigned* a, const unsigned* b) {
    asm volatile("mma.sync.aligned.m16n8k8.row.col.f32.tf32.tf32.f32 "
        "{%0,%1,%2,%3}, {%4,%5,%6,%7}, {%8,%9}, {%0,%1,%2,%3};"
        : "+f"(d[0]), "+f"(d[1]), "+f"(d[2]), "+f"(d[3])
        : "r"(a[0]), "r"(a[1]), "r"(a[2]), "r"(a[3]), "r"(b[0]), "r"(b[1]));
}
__device__ __forceinline__ void ldsm4(unsigned* r, unsigned addr) {
    asm volatile("ldmatrix.sync.aligned.m8n8.x4.shared.b16 {%0,%1,%2,%3}, [%4];"
        : "=r"(r[0]), "=r"(r[1]), "=r"(r[2]), "=r"(r[3]) : "r"(addr));
}
__device__ __forceinline__ void cp16(unsigned dst, const void* src) {
    asm volatile("cp.async.cg.shared.global [%0], [%1], 16;" :: "r"(dst), "l"(src) : "memory");
}
__device__ __forceinline__ unsigned smem_u32(const void* p) {
    return (unsigned)__cvta_generic_to_shared(p);
}

// ---------------- Weight pre-pass: Wt[n][k] = tf32(W[k][n]) ----------------
__global__ void wt_kernel(const float* __restrict__ Wq, const float* __restrict__ Wk,
                          const float* __restrict__ Wv, const float* __restrict__ Wo,
                          const float* __restrict__ W1, const float* __restrict__ W2,
                          const float* __restrict__ Wlm, unsigned* __restrict__ wt)
{
    __shared__ float tl[32][33];
    int id = blockIdx.z;
    int kt = blockIdx.x * 32, nt = blockIdx.y * 32;
    const float* src;
    unsigned* dst;
    int nsrc;
    if (id < 36) {
        int l = id / 6, m = id % 6;
        const float* bases[6] = {Wq, Wk, Wv, Wo, W1, W2};
        src = bases[m] + (size_t)l * CC;
        dst = wt + (size_t)id * CC;
        nsrc = 256;
    } else {
        if (nt >= 128) return;
        src = Wlm;
        dst = wt + 36 * CC;
        nsrc = 96;
    }
    int tx = threadIdx.x, ty = threadIdx.y;
    #pragma unroll
    for (int i = 0; i < 4; i++) {
        int k = kt + ty * 4 + i;
        int n = nt + tx;
        tl[ty * 4 + i][tx] = (n < nsrc) ? src[(size_t)k * nsrc + n] : 0.f;
    }
    __syncthreads();
    #pragma unroll
    for (int i = 0; i < 4; i++)
        dst[(size_t)(nt + ty * 4 + i) * 256 + kt + tx] = f2tf(tl[tx][ty * 4 + i]);
}

// ---------------- Embedding ----------------
__global__ void embed_kernel(const int* __restrict__ idx,
                             const float* __restrict__ tok,
                             const float* __restrict__ pos,
                             float* __restrict__ x, unsigned* __restrict__ xs) {
    int row = blockIdx.x;
    int c = threadIdx.x;
    int token = idx[row];
    float v = tok[token * Cn + c] + pos[(row & (Tn - 1)) * Cn + c];
    x[row * Cn + c] = v;
    xs[row * Cn + c] = f2tf(v);
}

// ---------------- GEMM (128x64): cp.async + ldmatrix ----------------
#define SSTR 36
#define ABUF_B (128*SSTR*4)
#define BBUF_B (64*SSTR*4)
#define GSMEM  (2*ABUF_B + 2*BBUF_B)

__device__ __forceinline__ void gemm_core(
    const unsigned* __restrict__ A, const unsigned* __restrict__ Wt,
    const float* __restrict__ bias, float* __restrict__ Cout,
    unsigned* __restrict__ shadow, float sscale,
    int Nd, int relu, int transT, char* smem)
{
    const unsigned sbase = smem_u32(smem);
    const int tid = threadIdx.x;
    const int lane = tid & 31, warp = tid >> 5;
    const int g = lane >> 2, t = lane & 3;
    const int wm = (warp & 3) * 32, wn = (warp >> 2) * 32;
    const int aRowBase = blockIdx.y * 128;
    const int bColBase = blockIdx.x * 64;

    float acc[2][4][4] = {};

    const unsigned* aSrc = A  + (size_t)(aRowBase + (tid >> 3)) * 256 + (tid & 7) * 4;
    const unsigned* bSrc = Wt + (size_t)(bColBase + (tid >> 3)) * 256 + (tid & 7) * 4;
    const unsigned aDst = sbase + (tid >> 3) * (SSTR * 4) + (tid & 7) * 16;
    const unsigned bDst = sbase + 2 * ABUF_B + (tid >> 3) * (SSTR * 4) + (tid & 7) * 16;

    unsigned aAddr0, aAddr1, bAddr0, bAddr1;
    {
        int l15 = lane & 15, lh = lane >> 4;
        aAddr0 = sbase + ((wm + l15) * SSTR + lh * 4) * 4;
        aAddr1 = aAddr0 + 16 * SSTR * 4;
        int brow = wn + ((lane >> 4) << 3) + (lane & 7);
        int bk = ((lane >> 3) & 1) * 4;
        bAddr0 = sbase + 2 * ABUF_B + (brow * SSTR + bk) * 4;
        bAddr1 = bAddr0 + 16 * SSTR * 4;
    }

    #pragma unroll
    for (int i = 0; i < 4; i++) cp16(aDst + i * 32 * SSTR * 4, aSrc + i * 32 * 256);
    #pragma unroll
    for (int i = 0; i < 2; i++) cp16(bDst + i * 32 * SSTR * 4, bSrc + i * 32 * 256);
    asm volatile("cp.async.commit_group;" ::: "memory");

    for (int kt = 0; kt < 8; kt++) {
        int cur = kt & 1;
        asm volatile("cp.async.wait_group 0;" ::: "memory");
        __syncthreads();

        if (kt < 7) {
            int koff = (kt + 1) * 32;
            unsigned ao = (1 - cur) * ABUF_B, bo = (1 - cur) * BBUF_B;
            #pragma unroll
            for (int i = 0; i < 4; i++)
                cp16(aDst + ao + i * 32 * SSTR * 4, aSrc + i * 32 * 256 + koff);
            #pragma unroll
            for (int i = 0; i < 2; i++)
                cp16(bDst + bo + i * 32 * SSTR * 4, bSrc + i * 32 * 256 + koff);
            asm volatile("cp.async.commit_group;" ::: "memory");
        }

        unsigned aob = cur * ABUF_B, bob = cur * BBUF_B;
        #pragma unroll
        for (int ks = 0; ks < 4; ks++) {
            unsigned a0[4], a1[4], b0[4], b1[4];
            ldsm4(a0, aAddr0 + aob + ks * 32);
            ldsm4(a1, aAddr1 + aob + ks * 32);
            ldsm4(b0, bAddr0 + bob + ks * 32);
            ldsm4(b1, bAddr1 + bob + ks * 32);
            mma_tf32(acc[0][0], a0, b0 + 0);
            mma_tf32(acc[0][1], a0, b0 + 2);
            mma_tf32(acc[0][2], a0, b1 + 0);
            mma_tf32(acc[0][3], a0, b1 + 2);
            mma_tf32(acc[1][0], a1, b0 + 0);
            mma_tf32(acc[1][1], a1, b0 + 2);
            mma_tf32(acc[1][2], a1, b1 + 0);
            mma_tf32(acc[1][3], a1, b1 + 2);
        }
    }

    if (!transT) {
        #pragma unroll
        for (int i = 0; i < 2; i++) {
            #pragma unroll
            for (int j = 0; j < 4; j++) {
                int col = bColBase + wn + j * 8 + t * 2;
                if (col >= Nd) continue;
                float bx = 0.f, by = 0.f;
                if (bias) { bx = bias[col]; by = bias[col + 1]; }
                int r0 = aRowBase + wm + i * 16 + g;
                float v0 = acc[i][j][0] + bx, v1 = acc[i][j][1] + by;
                float v2 = acc[i][j][2] + bx, v3 = acc[i][j][3] + by;
                if (relu) {
                    v0 = fmaxf(v0, 0.f); v1 = fmaxf(v1, 0.f);
                    v2 = fmaxf(v2, 0.f); v3 = fmaxf(v3, 0.f);
                }
                if (Cout) {
                    *(float2*)&Cout[(size_t)r0 * Nd + col]       = make_float2(v0, v1);
                    *(float2*)&Cout[(size_t)(r0 + 8) * Nd + col] = make_float2(v2, v3);
                }
                if (shadow) {
                    *(uint2*)&shadow[(size_t)r0 * Nd + col] =
                        make_uint2(f2tf(v0 * sscale), f2tf(v1 * sscale));
                    *(uint2*)&shadow[(size_t)(r0 + 8) * Nd + col] =
                        make_uint2(f2tf(v2 * sscale), f2tf(v3 * sscale));
                }
            }
        }
    } else {
        __syncthreads();
        float* patch = (float*)smem + warp * 1056;
        #pragma unroll
        for (int i = 0; i < 2; i++) {
            #pragma unroll
            for (int j = 0; j < 4; j++) {
                int c0 = j * 8 + t * 2;
                int r0 = i * 16 + g;
                patch[(c0    ) * 33 + r0    ] = acc[i][j][0];
                patch[(c0 + 1) * 33 + r0    ] = acc[i][j][1];
                patch[(c0    ) * 33 + r0 + 8] = acc[i][j][2];
                patch[(c0 + 1) * 33 + r0 + 8] = acc[i][j][3];
            }
        }
        __syncwarp();
        int rowG = aRowBase + wm;
        int bIdx = rowG >> 8;
        int tg = (lane & 7) * 4;
        int chi = lane >> 3;
        int tBase = (rowG & 255) + tg;
        #pragma unroll
        for (int jj = 0; jj < 8; jj++) {
            int c = jj * 4 + chi;
            uint4 v;
            v.x = f2tf(patch[c * 33 + tg + 0]);
            v.y = f2tf(patch[c * 33 + tg + 1]);
            v.z = f2tf(patch[c * 33 + tg + 2]);
            v.w = f2tf(patch[c * 33 + tg + 3]);
            *(uint4*)&shadow[(size_t)bIdx * (Cn * Tn) +
                             (size_t)(bColBase + wn + c) * Tn + tBase] = v;
        }
    }
}

__global__ __launch_bounds__(256, 3) void gemm_tc_kernel(
    const unsigned* __restrict__ A, const unsigned* __restrict__ Wt,
    const float* __restrict__ bias, float* __restrict__ Cout,
    unsigned* __restrict__ shadow, float sscale, int Nd, int relu)
{
    extern __shared__ char gsm[];
    gemm_core(A, Wt, bias, Cout, shadow, sscale, Nd, relu, 0, gsm);
}

__global__ __launch_bounds__(256, 3) void gemm_qkv_kernel(
    const unsigned* __restrict__ A, const unsigned* __restrict__ wtBase,
    unsigned* __restrict__ oq, unsigned* __restrict__ ok, unsigned* __restrict__ ovt)
{
    extern __shared__ char gsm[];
    int z = blockIdx.z;
    const unsigned* Wt = wtBase + (size_t)z * CC;
    unsigned* o = (z == 0) ? oq : (z == 1) ? ok : ovt;
    float scl = (z == 0) ? 0.0625f : 1.0f;
    gemm_core(A, Wt, nullptr, nullptr, o, scl, Cn, 0, (z == 2) ? 1 : 0, gsm);
}

// ---------------- Fused GEMM + residual + LayerNorm ----------------
// x = LN(x + A@W + bias); writes x (fp32) and xs (tf32). CTA 64(M) x 256(N),
// 8 warps as 2M x 4N (warp tile 32x64), BK=32 double buffered. One wave (256 CTAs).
#define LA_B (64*SSTR*4)             //  9216 B per A buffer
#define LB_B (256*SSTR*4)            // 36864 B per B buffer
#define LSMEM (2*LA_B + 2*LB_B)      // 92160 B

__global__ __launch_bounds__(256, 2) void gemm_ln_kernel(
    const unsigned* __restrict__ A, const unsigned* __restrict__ Wt,
    const float* __restrict__ bias, float* __restrict__ x,
    unsigned* __restrict__ xs, const float* __restrict__ lnw,
    const float* __restrict__ lnb)
{
    extern __shared__ char smem[];
    const unsigned sbase = smem_u32(smem);
    const int tid = threadIdx.x;
    const int lane = tid & 31, warp = tid >> 5;
    const int g = lane >> 2, t = lane & 3;
    const int wm = (warp & 1) * 32;
    const int wn = (warp >> 1) * 64;
    const int nw = warp >> 1;
    const int aRowBase = blockIdx.x * 64;

    float acc[2][8][4] = {};

    const unsigned* aSrc = A  + (size_t)(aRowBase + (tid >> 3)) * 256 + (tid & 7) * 4;
    const unsigned* bSrc = Wt + (size_t)(tid >> 3) * 256 + (tid & 7) * 4;
    const unsigned aDst = sbase + (tid >> 3) * (SSTR * 4) + (tid & 7) * 16;
    const unsigned bDst = sbase + 2 * LA_B + (tid >> 3) * (SSTR * 4) + (tid & 7) * 16;

    unsigned aAddr0, aAddr1, bAddr;
    {
        int l15 = lane & 15, lh = lane >> 4;
        aAddr0 = sbase + ((wm + l15) * SSTR + lh * 4) * 4;
        aAddr1 = aAddr0 + 16 * SSTR * 4;
        int brow = wn + ((lane >> 4) << 3) + (lane & 7);
        int bk = ((lane >> 3) & 1) * 4;
        bAddr = sbase + 2 * LA_B + (brow * SSTR + bk) * 4;
    }

    // prologue
    #pragma unroll
    for (int i = 0; i < 2; i++) cp16(aDst + i * 32 * SSTR * 4, aSrc + i * 32 * 256);
    #pragma unroll
    for (int i = 0; i < 8; i++) cp16(bDst + i * 32 * SSTR * 4, bSrc + i * 32 * 256);
    asm volatile("cp.async.commit_group;" ::: "memory");

    for (int kt = 0; kt < 8; kt++) {
        int cur = kt & 1;
        asm volatile("cp.async.wait_group 0;" ::: "memory");
        __syncthreads();

        if (kt < 7) {
            int koff = (kt + 1) * 32;
            unsigned ao = (1 - cur) * LA_B, bo = (1 - cur) * LB_B;
            #pragma unroll
            for (int i = 0; i < 2; i++)
                cp16(aDst + ao + i * 32 * SSTR * 4, aSrc + i * 32 * 256 + koff);
            #pragma unroll
            for (int i = 0; i < 8; i++)
                cp16(bDst + bo + i * 32 * SSTR * 4, bSrc + i * 32 * 256 + koff);
            asm volatile("cp.async.commit_group;" ::: "memory");
        }

        unsigned aob = cur * LA_B, bob = cur * LB_B;
        #pragma unroll
        for (int ks = 0; ks < 4; ks++) {
            unsigned a0[4], a1[4];
            ldsm4(a0, aAddr0 + aob + ks * 32);
            ldsm4(a1, aAddr1 + aob + ks * 32);
            #pragma unroll
            for (int np = 0; np < 4; np++) {
                unsigned bf[4];
                ldsm4(bf, bAddr + bob + np * (16 * SSTR * 4) + ks * 32);
                mma_tf32(acc[0][2 * np    ], a0, bf + 0);
                mma_tf32(acc[0][2 * np + 1], a0, bf + 2);
                mma_tf32(acc[1][2 * np    ], a1, bf + 0);
                mma_tf32(acc[1][2 * np + 1], a1, bf + 2);
            }
        }
    }

    // epilogue: v = acc + bias + residual; LN over the row
    float sr[4] = {0.f, 0.f, 0.f, 0.f}, qr[4] = {0.f, 0.f, 0.f, 0.f};
    #pragma unroll
    for (int i = 0; i < 2; i++) {
        int r0 = aRowBase + wm + i * 16 + g;
        #pragma unroll
        for (int j = 0; j < 8; j++) {
            int col = wn + j * 8 + t * 2;
            float bx = bias[col], by = bias[col + 1];
            float2 x0 = *(const float2*)&x[(size_t)r0 * Cn + col];
            float2 x1 = *(const float2*)&x[(size_t)(r0 + 8) * Cn + col];
            acc[i][j][0] += bx + x0.x; acc[i][j][1] += by + x0.y;
            acc[i][j][2] += bx + x1.x; acc[i][j][3] += by + x1.y;
            sr[i * 2]     += acc[i][j][0] + acc[i][j][1];
            qr[i * 2]     += acc[i][j][0] * acc[i][j][0] + acc[i][j][1] * acc[i][j][1];
            sr[i * 2 + 1] += acc[i][j][2] + acc[i][j][3];
            qr[i * 2 + 1] += acc[i][j][2] * acc[i][j][2] + acc[i][j][3] * acc[i][j][3];
        }
    }
    #pragma unroll
    for (int o = 1; o <= 2; o <<= 1) {
        #pragma unroll
        for (int r = 0; r < 4; r++) {
            sr[r] += __shfl_xor_sync(0xFFFFFFFFu, sr[r], o);
            qr[r] += __shfl_xor_sync(0xFFFFFFFFu, qr[r], o);
        }
    }
    __syncthreads();   // smem staging no longer needed; reuse for reduction
    float* redS = (float*)smem;
    float* redQ = redS + 256;
    if (t == 0) {
        #pragma unroll
        for (int i = 0; i < 2; i++) {
            int lr = wm + i * 16 + g;
            redS[lr * 4 + nw] = sr[i * 2];       redQ[lr * 4 + nw] = qr[i * 2];
            redS[(lr + 8) * 4 + nw] = sr[i * 2 + 1]; redQ[(lr + 8) * 4 + nw] = qr[i * 2 + 1];
        }
    }
    __syncthreads();

    float mean[4], rinv[4];
    #pragma unroll
    for (int i = 0; i < 2; i++) {
        #pragma unroll
        for (int hf = 0; hf < 2; hf++) {
            int lr = wm + i * 16 + g + hf * 8;
            float S = redS[lr * 4 + 0] + redS[lr * 4 + 1] + redS[lr * 4 + 2] + redS[lr * 4 + 3];
            float Q = redQ[lr * 4 + 0] + redQ[lr * 4 + 1] + redQ[lr * 4 + 2] + redQ[lr * 4 + 3];
            float m = S * (1.f / Cn);
            mean[i * 2 + hf] = m;
            rinv[i * 2 + hf] = rsqrtf(Q * (1.f / Cn) - m * m + EPSF);
        }
    }

    #pragma unroll
    for (int i = 0; i < 2; i++) {
        int r0 = aRowBase + wm + i * 16 + g;
        float m0 = mean[i * 2], r0i = rinv[i * 2];
        float m1 = mean[i * 2 + 1], r1i = rinv[i * 2 + 1];
        #pragma unroll
        for (int j = 0; j < 8; j++) {
            int col = wn + j * 8 + t * 2;
            float w0 = lnw[col], w1 = lnw[col + 1];
            float c0 = lnb[col], c1 = lnb[col + 1];
            float o0 = (acc[i][j][0] - m0) * r0i * w0 + c0;
            float o1 = (acc[i][j][1] - m0) * r0i * w1 + c1;
            float o2 = (acc[i][j][2] - m1) * r1i * w0 + c0;
            float o3 = (acc[i][j][3] - m1) * r1i * w1 + c1;
            *(float2*)&x[(size_t)r0 * Cn + col]       = make_float2(o0, o1);
            *(float2*)&x[(size_t)(r0 + 8) * Cn + col] = make_float2(o2, o3);
            *(uint2*)&xs[(size_t)r0 * Cn + col]       = make_uint2(f2tf(o0), f2tf(o1));
            *(uint2*)&xs[(size_t)(r0 + 8) * Cn + col] = make_uint2(f2tf(o2), f2tf(o3));
        }
    }
}

// ---------------- Tensor-core flash attention (unchanged from R15) ----------------
#define AKSTR 36
#define AVSTR 68
#define APSTR 68
#define KBUF  (64*AKSTR)
#define VBUF  (32*AVSTR)
#define ASMEM ((2*KBUF + 2*VBUF + 4*16*APSTR) * 4)

__global__ __launch_bounds__(128, 4) void attn_tc_kernel(
    const unsigned* __restrict__ Qs, const unsigned* __restrict__ Kg,
    const unsigned* __restrict__ VTg, unsigned* __restrict__ Os)
{
    extern __shared__ unsigned dsm[];
    unsigned* sPw = dsm + 2 * KBUF + 2 * VBUF;

    int qb = 3 - blockIdx.x;
    int h  = blockIdx.y;
    int b  = blockIdx.z;
    int tid = threadIdx.x;
    int warp = tid >> 5, lane = tid & 31;
    int g = lane >> 2, t = lane & 3;
    int hsoff = h * HSn;
    int qrow = qb * 64 + warp * 16;

    unsigned qa[4][4];
    {
        const unsigned* Qb = Qs + (size_t)(b * Tn + qrow) * Cn + hsoff;
        #pragma unroll
        for (int ks = 0; ks < 4; ks++) {
            qa[ks][0] = Qb[(size_t)g       * Cn + ks * 8 + t];
            qa[ks][1] = Qb[(size_t)(g + 8) * Cn + ks * 8 + t];
            qa[ks][2] = Qb[(size_t)g       * Cn + ks * 8 + t + 4];
            qa[ks][3] = Qb[(size_t)(g + 8) * Cn + ks * 8 + t + 4];
        }
    }

    const unsigned sK0 = smem_u32(dsm);
    const unsigned sV0 = sK0 + 2 * KBUF * 4;
    const unsigned sP  = sV0 + 2 * VBUF * 4 + warp * (16 * APSTR * 4);
    unsigned* Pw = sPw + warp * (16 * APSTR);

    const unsigned* kSrc = Kg + (size_t)(b * Tn + (tid >> 3)) * Cn + hsoff + (tid & 7) * 4;
    const unsigned  kDst = sK0 + (tid >> 3) * (AKSTR * 4) + (tid & 7) * 16;
    const unsigned* vSrc = VTg + ((size_t)b * Cn + hsoff + (tid >> 4)) * Tn + (tid & 15) * 4;
    const unsigned  vDst = sV0 + (tid >> 4) * (AVSTR * 4) + (tid & 15) * 16;

    const unsigned kfAddr = sK0 + ((((lane >> 4) << 3) + (lane & 7)) * AKSTR + ((lane >> 3) & 1) * 4) * 4;
    const unsigned vfAddr = sV0 + ((((lane >> 4) << 3) + (lane & 7)) * AVSTR + ((lane >> 3) & 1) * 4) * 4;
    const unsigned pfAddr = sP + ((lane & 15) * APSTR + (lane >> 4) * 4) * 4;

    float oa[4][4] = {};
    float m0 = -1e30f, m1 = -1e30f, l0 = 0.f, l1 = 0.f;

    #pragma unroll
    for (int i = 0; i < 4; i++) cp16(kDst + i * 16 * AKSTR * 4, kSrc + (size_t)i * 16 * Cn);
    #pragma unroll
    for (int i = 0; i < 4; i++) cp16(vDst + i * 8 * AVSTR * 4, vSrc + (size_t)i * 8 * Tn);
    asm volatile("cp.async.commit_group;" ::: "memory");

    for (int kc = 0; kc <= qb; kc++) {
        int cur = kc & 1;
        if (kc < qb) {
            int nxt = 1 - cur;
            int koff = (kc + 1) * 64;
            #pragma unroll
            for (int i = 0; i < 4; i++)
                cp16(kDst + nxt * KBUF * 4 + i * 16 * AKSTR * 4,
                     kSrc + (size_t)(koff + i * 16) * Cn);
            #pragma unroll
            for (int i = 0; i < 4; i++)
                cp16(vDst + nxt * VBUF * 4 + i * 8 * AVSTR * 4,
                     vSrc + koff + (size_t)i * 8 * Tn);
            asm volatile("cp.async.commit_group;" ::: "memory");
            asm volatile("cp.async.wait_group 1;" ::: "memory");
        } else {
            asm volatile("cp.async.wait_group 0;" ::: "memory");
        }
        __syncthreads();

        unsigned ko = cur * KBUF * 4, vo = cur * VBUF * 4;

        float sc[8][4];
        #pragma unroll
        for (int nf = 0; nf < 8; nf++)
            #pragma unroll
            for (int j = 0; j < 4; j++) sc[nf][j] = 0.f;
        #pragma unroll
        for (int ks = 0; ks < 4; ks++) {
            #pragma unroll
            for (int np = 0; np < 4; np++) {
                unsigned bf[4];
                ldsm4(bf, kfAddr + ko + np * (16 * AKSTR * 4) + ks * 32);
                mma_tf32(sc[2 * np    ], qa[ks], bf + 0);
                mma_tf32(sc[2 * np + 1], qa[ks], bf + 2);
            }
        }

        if (kc == qb) {
            int r0 = warp * 16 + g;
            #pragma unroll
            for (int nf = 0; nf < 8; nf++) {
                int c0 = nf * 8 + 2 * t;
                if (c0     > r0    ) sc[nf][0] = -1e30f;
                if (c0 + 1 > r0    ) sc[nf][1] = -1e30f;
                if (c0     > r0 + 8) sc[nf][2] = -1e30f;
                if (c0 + 1 > r0 + 8) sc[nf][3] = -1e30f;
            }
        }

        float mx0 = -1e30f, mx1 = -1e30f;
        #pragma unroll
        for (int nf = 0; nf < 8; nf++) {
            mx0 = fmaxf(mx0, fmaxf(sc[nf][0], sc[nf][1]));
            mx1 = fmaxf(mx1, fmaxf(sc[nf][2], sc[nf][3]));
        }
        #pragma unroll
        for (int o = 1; o <= 2; o <<= 1) {
            mx0 = fmaxf(mx0, __shfl_xor_sync(0xFFFFFFFFu, mx0, o));
            mx1 = fmaxf(mx1, __shfl_xor_sync(0xFFFFFFFFu, mx1, o));
        }
        float nm0 = fmaxf(m0, mx0), nm1 = fmaxf(m1, mx1);
        float al0 = __expf(m0 - nm0), al1 = __expf(m1 - nm1);

        float s0 = 0.f, s1 = 0.f;
        #pragma unroll
        for (int nf = 0; nf < 8; nf++) {
            float p0 = __expf(sc[nf][0] - nm0);
            float p1 = __expf(sc[nf][1] - nm0);
            float p2 = __expf(sc[nf][2] - nm1);
            float p3 = __expf(sc[nf][3] - nm1);
            s0 += p0 + p1; s1 += p2 + p3;
            *(uint2*)&Pw[(g    ) * APSTR + nf * 8 + 2 * t] = make_uint2(f2tf(p0), f2tf(p1));
            *(uint2*)&Pw[(g + 8) * APSTR + nf * 8 + 2 * t] = make_uint2(f2tf(p2), f2tf(p3));
        }
        #pragma unroll
        for (int o = 1; o <= 2; o <<= 1) {
            s0 += __shfl_xor_sync(0xFFFFFFFFu, s0, o);
            s1 += __shfl_xor_sync(0xFFFFFFFFu, s1, o);
        }
        l0 = l0 * al0 + s0;
        l1 = l1 * al1 + s1;
        m0 = nm0; m1 = nm1;

        #pragma unroll
        for (int nf = 0; nf < 4; nf++) {
            oa[nf][0] *= al0; oa[nf][1] *= al0;
            oa[nf][2] *= al1; oa[nf][3] *= al1;
        }
        __syncwarp();

        #pragma unroll
        for (int ks = 0; ks < 8; ks++) {
            unsigned pa[4], vb0[4], vb1[4];
            ldsm4(pa,  pfAddr + ks * 32);
            ldsm4(vb0, vfAddr + vo + ks * 32);
            ldsm4(vb1, vfAddr + vo + 16 * AVSTR * 4 + ks * 32);
            mma_tf32(oa[0], pa, vb0 + 0);
            mma_tf32(oa[1], pa, vb0 + 2);
            mma_tf32(oa[2], pa, vb1 + 0);
            mma_tf32(oa[3], pa, vb1 + 2);
        }
        __syncthreads();
    }

    float i0 = 1.f / l0, i1 = 1.f / l1;
    unsigned* Ob = Os + (size_t)(b * Tn + qrow) * Cn + hsoff;
    #pragma unroll
    for (int nf = 0; nf < 4; nf++) {
        int c = nf * 8 + 2 * t;
        *(uint2*)&Ob[(size_t)g       * Cn + c] =
            make_uint2(f2tf(oa[nf][0] * i0), f2tf(oa[nf][1] * i0));
        *(uint2*)&Ob[(size_t)(g + 8) * Cn + c] =
            make_uint2(f2tf(oa[nf][2] * i1), f2tf(oa[nf][3] * i1));
    }
}

// ---------------- plain LayerNorm (final lnf only) ----------------
__global__ __launch_bounds__(256) void add_ln_kernel(
    float* __restrict__ x, const float* __restrict__ t,
    const float* __restrict__ w, const float* __restrict__ bb,
    unsigned* __restrict__ xs)
{
    int row = blockIdx.x;
    int c = threadIdx.x;
    float v = x[(size_t)row * Cn + c];
    if (t) v += t[(size_t)row * Cn + c];

    float s = v, s2 = v * v;
    #pragma unroll
    for (int o = 16; o; o >>= 1) {
        s  += __shfl_xor_sync(0xFFFFFFFFu, s, o);
        s2 += __shfl_xor_sync(0xFFFFFFFFu, s2, o);
    }
    __shared__ float sh[16];
    int warp = c >> 5, lane = c & 31;
    if (lane == 0) { sh[warp] = s; sh[warp + 8] = s2; }
    __syncthreads();
    float sum = 0.f, sum2 = 0.f;
    #pragma unroll
    for (int i = 0; i < 8; i++) { sum += sh[i]; sum2 += sh[i + 8]; }

    float mean = sum * (1.f / Cn);
    float var  = sum2 * (1.f / Cn) - mean * mean;
    float r = rsqrtf(var + EPSF);
    float out = (v - mean) * r * w[c] + bb[c];
    x[(size_t)row * Cn + c] = out;
    xs[(size_t)row * Cn + c] = f2tf(out);
}

// ---------------- Loss ----------------
__global__ __launch_bounds__(256) void loss_row_kernel(
    const float* __restrict__ logits, const int* __restrict__ target,
    float* __restrict__ nll)
{
    int gwarp = (blockIdx.x * blockDim.x + threadIdx.x) >> 5;
    int lane = threadIdx.x & 31;
    if (gwarp >= NROWS) return;
    const float* lg = logits + (size_t)gwarp * Vn;
    float v0 = lg[lane], v1 = lg[lane + 32], v2 = lg[lane + 64];
    float mx = fmaxf(v0, fmaxf(v1, v2));
    #pragma unroll
    for (int o = 16; o; o >>= 1) mx = fmaxf(mx, __shfl_xor_sync(0xFFFFFFFFu, mx, o));
    float s = __expf(v0 - mx) + __expf(v1 - mx) + __expf(v2 - mx);
    #pragma unroll
    for (int o = 16; o; o >>= 1) s += __shfl_xor_sync(0xFFFFFFFFu, s, o);
    if (lane == 0) {
        float lse = mx + logf(s);
        nll[gwarp] = lse - lg[target[gwarp]];
    }
}

__global__ __launch_bounds__(256) void loss_reduce_kernel(
    const float* __restrict__ nll, float* __restrict__ out)
{
    __shared__ float sh[256];
    float s = 0.f;
    for (int i = threadIdx.x; i < NROWS; i += 256) s += nll[i];
    sh[threadIdx.x] = s;
    __syncthreads();
    for (int st = 128; st; st >>= 1) {
        if (threadIdx.x < st) sh[threadIdx.x] += sh[threadIdx.x + st];
        __syncthreads();
    }
    if (threadIdx.x == 0) out[0] = sh[0] * (1.f / NROWS);
}

// ---------------- Host-side launch sequence ----------------
extern "C" void kernel_launch(void* const* d_in, const int* in_sizes, int n_in,
                              void* d_out, int out_size) {
    const int*   idx    = (const int*)  d_in[0];
    const int*   target = (const int*)  d_in[1];
    const float* tok    = (const float*)d_in[2];
    const float* pos    = (const float*)d_in[3];
    const float* Wq     = (const float*)d_in[4];
    const float* Wk     = (const float*)d_in[5];
    const float* Wv     = (const float*)d_in[6];
    const float* Wo     = (const float*)d_in[7];
    const float* bo     = (const float*)d_in[8];
    const float* W1     = (const float*)d_in[9];
    const float* b1     = (const float*)d_in[10];
    const float* W2     = (const float*)d_in[11];
    const float* b2     = (const float*)d_in[12];
    const float* ln1w   = (const float*)d_in[13];
    const float* ln1b   = (const float*)d_in[14];
    const float* ln2w   = (const float*)d_in[15];
    const float* ln2b   = (const float*)d_in[16];
    const float* lnfw   = (const float*)d_in[17];
    const float* lnfb   = (const float*)d_in[18];
    const float* Wlm    = (const float*)d_in[19];
    const float* blm    = (const float*)d_in[20];

    float* logits = (float*)d_out;

    float* s = nullptr;
    cudaGetSymbolAddress((void**)&s, g_scratch);
    unsigned* sh = nullptr;
    cudaGetSymbolAddress((void**)&sh, g_shadow);
    unsigned* wt = nullptr;
    cudaGetSymbolAddress((void**)&wt, g_wt);

    float* x   = s;
    float* nll = s + (size_t)NROWS * Cn;
    unsigned* xs  = sh;
    unsigned* qs  = sh + 1 * (size_t)NROWS * Cn;
    unsigned* ksb = sh + 2 * (size_t)NROWS * Cn;
    unsigned* vts = sh + 3 * (size_t)NROWS * Cn;
    unsigned* bds = sh + 4 * (size_t)NROWS * Cn;
    unsigned* bbs = sh + 5 * (size_t)NROWS * Cn;

    cudaFuncSetAttribute(gemm_tc_kernel,
                         cudaFuncAttributeMaxDynamicSharedMemorySize, GSMEM);
    cudaFuncSetAttribute(gemm_qkv_kernel,
                         cudaFuncAttributeMaxDynamicSharedMemorySize, GSMEM);
    cudaFuncSetAttribute(gemm_ln_kernel,
                         cudaFuncAttributeMaxDynamicSharedMemorySize, LSMEM);
    cudaFuncSetAttribute(attn_tc_kernel,
                         cudaFuncAttributeMaxDynamicSharedMemorySize, ASMEM);

    dim3 gemmGridC(Cn / 64, NROWS / 128);
    dim3 gemmGridV((Vn + 63) / 64, NROWS / 128);
    dim3 qkvGrid(Cn / 64, NROWS / 128, 3);
    dim3 attnGrid(4, Hn, Bn);

    wt_kernel<<<dim3(8, 8, 37), dim3(32, 8)>>>(Wq, Wk, Wv, Wo, W1, W2, Wlm, wt);
    embed_kernel<<<NROWS, 256>>>(idx, tok, pos, x, xs);

    for (int l = 0; l < Ln; l++) {
        const unsigned* wtl = wt + (size_t)l * 6 * CC;

        gemm_qkv_kernel<<<qkvGrid, 256, GSMEM>>>(xs, wtl, qs, ksb, vts);

        attn_tc_kernel<<<attnGrid, 128, ASMEM>>>(qs, ksb, vts, bds);

        gemm_ln_kernel<<<NROWS / 64, 256, LSMEM>>>(bds, wtl + 3 * CC,
            bo + (size_t)l * Cn, x, xs,
            ln1w + (size_t)l * Cn, ln1b + (size_t)l * Cn);

        gemm_tc_kernel<<<gemmGridC, 256, GSMEM>>>(xs, wtl + 4 * CC,
            b1 + (size_t)l * Cn, nullptr, bbs, 1.f, Cn, 1);

        gemm_ln_kernel<<<NROWS / 64, 256, LSMEM>>>(bbs, wtl + 5 * CC,
            b2 + (size_t)l * Cn, x, xs,
            ln2w + (size_t)l * Cn, ln2b + (size_t)l * Cn);
    }

    add_ln_kernel<<<NROWS, 256>>>(x, nullptr, lnfw, lnfb, xs);
    gemm_tc_kernel<<<gemmGridV, 256, GSMEM>>>(xs, wt + 36 * CC, blm,
        logits, nullptr, 1.f, Vn, 0);

    if (out_size > NROWS * Vn) {
        loss_row_kernel<<<NROWS / 8, 256>>>(logits, target, nll);
        loss_reduce_kernel<<<1, 256>>>(nll, logits + (size_t)NROWS * Vn);
    }
}

// round 17
// speedup vs baseline: 1.4616x; 1.0220x over previous
#include <cuda_runtime.h>
#include <cuda_bf16.h>

// ---------------- Problem constants ----------------
#define Bn    64
#define Tn    256
#define Cn    256
#define Hn    8
#define HSn   32
#define Ln    6
#define Vn    96
#define NROWS (Bn*Tn)
#define CC    (Cn*Cn)
#define EPSF  1e-5f
#define KK    256

// ---------------- Scratch ----------------
__device__ float    g_scratch[NROWS * Cn + NROWS];        // x, nll
__device__ unsigned g_shadow [6 * NROWS * Cn];            // xs, qs, ks, vt, bds, bbs
__device__ unsigned g_wt     [36 * CC + 128 * 256];       // tf32 W^T

// ---------------- helpers ----------------
__device__ __forceinline__ unsigned f2tf(float f) {
    unsigned u;
    asm("cvt.rna.tf32.f32 %0, %1;" : "=r"(u) : "f"(f));
    return u;
}
__device__ __forceinline__ void mma_tf32(float* d, const unsigned* a, const unsigned* b) {
    asm volatile("mma.sync.aligned.m16n8k8.row.col.f32.tf32.tf32.f32 "
        "{%0,%1,%2,%3}, {%4,%5,%6,%7}, {%8,%9}, {%0,%1,%2,%3};"
        : "+f"(d[0]), "+f"(d[1]), "+f"(d[2]), "+f"(d[3])
        : "r"(a[0]), "r"(a[1]), "r"(a[2]), "r"(a[3]), "r"(b[0]), "r"(b[1]));
}
__device__ __forceinline__ void ldsm4(unsigned* r, unsigned addr) {
    asm volatile("ldmatrix.sync.aligned.m8n8.x4.shared.b16 {%0,%1,%2,%3}, [%4];"
        : "=r"(r[0]), "=r"(r[1]), "=r"(r[2]), "=r"(r[3]) : "r"(addr));
}
__device__ __forceinline__ void cp16(unsigned dst, const void* src) {
    asm volatile("cp.async.cg.shared.global [%0], [%1], 16;" :: "r"(dst), "l"(src) : "memory");
}
__device__ __forceinline__ unsigned smem_u32(const void* p) {
    return (unsigned)__cvta_generic_to_shared(p);
}

// ---------------- Weight pre-pass: Wt[n][k] = tf32(W[k][n]) ----------------
__global__ void wt_kernel(const float* __restrict__ Wq, const float* __restrict__ Wk,
                          const float* __restrict__ Wv, const float* __restrict__ Wo,
                          const float* __restrict__ W1, const float* __restrict__ W2,
                          const float* __restrict__ Wlm, unsigned* __restrict__ wt)
{
    __shared__ float tl[32][33];
    int id = blockIdx.z;
    int kt = blockIdx.x * 32, nt = blockIdx.y * 32;
    const float* src;
    unsigned* dst;
    int nsrc;
    if (id < 36) {
        int l = id / 6, m = id % 6;
        const float* bases[6] = {Wq, Wk, Wv, Wo, W1, W2};
        src = bases[m] + (size_t)l * CC;
        dst = wt + (size_t)id * CC;
        nsrc = 256;
    } else {
        if (nt >= 128) return;
        src = Wlm;
        dst = wt + 36 * CC;
        nsrc = 96;
    }
    int tx = threadIdx.x, ty = threadIdx.y;
    #pragma unroll
    for (int i = 0; i < 4; i++) {
        int k = kt + ty * 4 + i;
        int n = nt + tx;
        tl[ty * 4 + i][tx] = (n < nsrc) ? src[(size_t)k * nsrc + n] : 0.f;
    }
    __syncthreads();
    #pragma unroll
    for (int i = 0; i < 4; i++)
        dst[(size_t)(nt + ty * 4 + i) * 256 + kt + tx] = f2tf(tl[tx][ty * 4 + i]);
}

// ---------------- Embedding ----------------
__global__ void embed_kernel(const int* __restrict__ idx,
                             const float* __restrict__ tok,
                             const float* __restrict__ pos,
                             float* __restrict__ x, unsigned* __restrict__ xs) {
    int row = blockIdx.x;
    int c = threadIdx.x;
    int token = idx[row];
    float v = tok[token * Cn + c] + pos[(row & (Tn - 1)) * Cn + c];
    x[row * Cn + c] = v;
    xs[row * Cn + c] = f2tf(v);
}

// ---------------- GEMM (128x64): cp.async + ldmatrix ----------------
#define SSTR 36
#define ABUF_B (128*SSTR*4)
#define BBUF_B (64*SSTR*4)
#define GSMEM  (2*ABUF_B + 2*BBUF_B)

__device__ __forceinline__ void gemm_core(
    const unsigned* __restrict__ A, const unsigned* __restrict__ Wt,
    const float* __restrict__ bias, float* __restrict__ Cout,
    unsigned* __restrict__ shadow, float sscale,
    int Nd, int relu, int transT, char* smem)
{
    const unsigned sbase = smem_u32(smem);
    const int tid = threadIdx.x;
    const int lane = tid & 31, warp = tid >> 5;
    const int g = lane >> 2, t = lane & 3;
    const int wm = (warp & 3) * 32, wn = (warp >> 2) * 32;
    const int aRowBase = blockIdx.y * 128;
    const int bColBase = blockIdx.x * 64;

    float acc[2][4][4] = {};

    const unsigned* aSrc = A  + (size_t)(aRowBase + (tid >> 3)) * 256 + (tid & 7) * 4;
    const unsigned* bSrc = Wt + (size_t)(bColBase + (tid >> 3)) * 256 + (tid & 7) * 4;
    const unsigned aDst = sbase + (tid >> 3) * (SSTR * 4) + (tid & 7) * 16;
    const unsigned bDst = sbase + 2 * ABUF_B + (tid >> 3) * (SSTR * 4) + (tid & 7) * 16;

    unsigned aAddr0, aAddr1, bAddr0, bAddr1;
    {
        int l15 = lane & 15, lh = lane >> 4;
        aAddr0 = sbase + ((wm + l15) * SSTR + lh * 4) * 4;
        aAddr1 = aAddr0 + 16 * SSTR * 4;
        int brow = wn + ((lane >> 4) << 3) + (lane & 7);
        int bk = ((lane >> 3) & 1) * 4;
        bAddr0 = sbase + 2 * ABUF_B + (brow * SSTR + bk) * 4;
        bAddr1 = bAddr0 + 16 * SSTR * 4;
    }

    #pragma unroll
    for (int i = 0; i < 4; i++) cp16(aDst + i * 32 * SSTR * 4, aSrc + i * 32 * 256);
    #pragma unroll
    for (int i = 0; i < 2; i++) cp16(bDst + i * 32 * SSTR * 4, bSrc + i * 32 * 256);
    asm volatile("cp.async.commit_group;" ::: "memory");

    for (int kt = 0; kt < 8; kt++) {
        int cur = kt & 1;
        asm volatile("cp.async.wait_group 0;" ::: "memory");
        __syncthreads();

        if (kt < 7) {
            int koff = (kt + 1) * 32;
            unsigned ao = (1 - cur) * ABUF_B, bo = (1 - cur) * BBUF_B;
            #pragma unroll
            for (int i = 0; i < 4; i++)
                cp16(aDst + ao + i * 32 * SSTR * 4, aSrc + i * 32 * 256 + koff);
            #pragma unroll
            for (int i = 0; i < 2; i++)
                cp16(bDst + bo + i * 32 * SSTR * 4, bSrc + i * 32 * 256 + koff);
            asm volatile("cp.async.commit_group;" ::: "memory");
        }

        unsigned aob = cur * ABUF_B, bob = cur * BBUF_B;
        #pragma unroll
        for (int ks = 0; ks < 4; ks++) {
            unsigned a0[4], a1[4], b0[4], b1[4];
            ldsm4(a0, aAddr0 + aob + ks * 32);
            ldsm4(a1, aAddr1 + aob + ks * 32);
            ldsm4(b0, bAddr0 + bob + ks * 32);
            ldsm4(b1, bAddr1 + bob + ks * 32);
            mma_tf32(acc[0][0], a0, b0 + 0);
            mma_tf32(acc[0][1], a0, b0 + 2);
            mma_tf32(acc[0][2], a0, b1 + 0);
            mma_tf32(acc[0][3], a0, b1 + 2);
            mma_tf32(acc[1][0], a1, b0 + 0);
            mma_tf32(acc[1][1], a1, b0 + 2);
            mma_tf32(acc[1][2], a1, b1 + 0);
            mma_tf32(acc[1][3], a1, b1 + 2);
        }
    }

    if (!transT) {
        #pragma unroll
        for (int i = 0; i < 2; i++) {
            #pragma unroll
            for (int j = 0; j < 4; j++) {
                int col = bColBase + wn + j * 8 + t * 2;
                if (col >= Nd) continue;
                float bx = 0.f, by = 0.f;
                if (bias) { bx = bias[col]; by = bias[col + 1]; }
                int r0 = aRowBase + wm + i * 16 + g;
                float v0 = acc[i][j][0] + bx, v1 = acc[i][j][1] + by;
                float v2 = acc[i][j][2] + bx, v3 = acc[i][j][3] + by;
                if (relu) {
                    v0 = fmaxf(v0, 0.f); v1 = fmaxf(v1, 0.f);
                    v2 = fmaxf(v2, 0.f); v3 = fmaxf(v3, 0.f);
                }
                if (Cout) {
                    *(float2*)&Cout[(size_t)r0 * Nd + col]       = make_float2(v0, v1);
                    *(float2*)&Cout[(size_t)(r0 + 8) * Nd + col] = make_float2(v2, v3);
                }
                if (shadow) {
                    *(uint2*)&shadow[(size_t)r0 * Nd + col] =
                        make_uint2(f2tf(v0 * sscale), f2tf(v1 * sscale));
                    *(uint2*)&shadow[(size_t)(r0 + 8) * Nd + col] =
                        make_uint2(f2tf(v2 * sscale), f2tf(v3 * sscale));
                }
            }
        }
    } else {
        __syncthreads();
        float* patch = (float*)smem + warp * 1056;
        #pragma unroll
        for (int i = 0; i < 2; i++) {
            #pragma unroll
            for (int j = 0; j < 4; j++) {
                int c0 = j * 8 + t * 2;
                int r0 = i * 16 + g;
                patch[(c0    ) * 33 + r0    ] = acc[i][j][0];
                patch[(c0 + 1) * 33 + r0    ] = acc[i][j][1];
                patch[(c0    ) * 33 + r0 + 8] = acc[i][j][2];
                patch[(c0 + 1) * 33 + r0 + 8] = acc[i][j][3];
            }
        }
        __syncwarp();
        int rowG = aRowBase + wm;
        int bIdx = rowG >> 8;
        int tg = (lane & 7) * 4;
        int chi = lane >> 3;
        int tBase = (rowG & 255) + tg;
        #pragma unroll
        for (int jj = 0; jj < 8; jj++) {
            int c = jj * 4 + chi;
            uint4 v;
            v.x = f2tf(patch[c * 33 + tg + 0]);
            v.y = f2tf(patch[c * 33 + tg + 1]);
            v.z = f2tf(patch[c * 33 + tg + 2]);
            v.w = f2tf(patch[c * 33 + tg + 3]);
            *(uint4*)&shadow[(size_t)bIdx * (Cn * Tn) +
                             (size_t)(bColBase + wn + c) * Tn + tBase] = v;
        }
    }
}

__global__ __launch_bounds__(256, 3) void gemm_tc_kernel(
    const unsigned* __restrict__ A, const unsigned* __restrict__ Wt,
    const float* __restrict__ bias, float* __restrict__ Cout,
    unsigned* __restrict__ shadow, float sscale, int Nd, int relu)
{
    extern __shared__ char gsm[];
    gemm_core(A, Wt, bias, Cout, shadow, sscale, Nd, relu, 0, gsm);
}

__global__ __launch_bounds__(256, 3) void gemm_qkv_kernel(
    const unsigned* __restrict__ A, const unsigned* __restrict__ wtBase,
    unsigned* __restrict__ oq, unsigned* __restrict__ ok, unsigned* __restrict__ ovt)
{
    extern __shared__ char gsm[];
    int z = blockIdx.z;
    const unsigned* Wt = wtBase + (size_t)z * CC;
    unsigned* o = (z == 0) ? oq : (z == 1) ? ok : ovt;
    float scl = (z == 0) ? 0.0625f : 1.0f;
    gemm_core(A, Wt, nullptr, nullptr, o, scl, Cn, 0, (z == 2) ? 1 : 0, gsm);
}

// ---------------- Fused GEMM + residual + LayerNorm (+ optional final LN) ----------------
// x = LN(x + A@W + bias); optionally xs = tf32(LNf(x)) with no fp32 x write.
#define LA_B (64*SSTR*4)
#define LB_B (256*SSTR*4)
#define LSMEM (2*LA_B + 2*LB_B)

__global__ __launch_bounds__(256, 2) void gemm_ln_kernel(
    const unsigned* __restrict__ A, const unsigned* __restrict__ Wt,
    const float* __restrict__ bias, float* __restrict__ x,
    unsigned* __restrict__ xs, const float* __restrict__ lnw,
    const float* __restrict__ lnb, const float* __restrict__ lnfw,
    const float* __restrict__ lnfb)
{
    extern __shared__ char smem[];
    const unsigned sbase = smem_u32(smem);
    const int tid = threadIdx.x;
    const int lane = tid & 31, warp = tid >> 5;
    const int g = lane >> 2, t = lane & 3;
    const int wm = (warp & 1) * 32;
    const int wn = (warp >> 1) * 64;
    const int nw = warp >> 1;
    const int aRowBase = blockIdx.x * 64;

    float acc[2][8][4] = {};

    const unsigned* aSrc = A  + (size_t)(aRowBase + (tid >> 3)) * 256 + (tid & 7) * 4;
    const unsigned* bSrc = Wt + (size_t)(tid >> 3) * 256 + (tid & 7) * 4;
    const unsigned aDst = sbase + (tid >> 3) * (SSTR * 4) + (tid & 7) * 16;
    const unsigned bDst = sbase + 2 * LA_B + (tid >> 3) * (SSTR * 4) + (tid & 7) * 16;

    unsigned aAddr0, aAddr1, bAddr;
    {
        int l15 = lane & 15, lh = lane >> 4;
        aAddr0 = sbase + ((wm + l15) * SSTR + lh * 4) * 4;
        aAddr1 = aAddr0 + 16 * SSTR * 4;
        int brow = wn + ((lane >> 4) << 3) + (lane & 7);
        int bk = ((lane >> 3) & 1) * 4;
        bAddr = sbase + 2 * LA_B + (brow * SSTR + bk) * 4;
    }

    #pragma unroll
    for (int i = 0; i < 2; i++) cp16(aDst + i * 32 * SSTR * 4, aSrc + i * 32 * 256);
    #pragma unroll
    for (int i = 0; i < 8; i++) cp16(bDst + i * 32 * SSTR * 4, bSrc + i * 32 * 256);
    asm volatile("cp.async.commit_group;" ::: "memory");

    for (int kt = 0; kt < 8; kt++) {
        int cur = kt & 1;
        asm volatile("cp.async.wait_group 0;" ::: "memory");
        __syncthreads();

        if (kt < 7) {
            int koff = (kt + 1) * 32;
            unsigned ao = (1 - cur) * LA_B, bo = (1 - cur) * LB_B;
            #pragma unroll
            for (int i = 0; i < 2; i++)
                cp16(aDst + ao + i * 32 * SSTR * 4, aSrc + i * 32 * 256 + koff);
            #pragma unroll
            for (int i = 0; i < 8; i++)
                cp16(bDst + bo + i * 32 * SSTR * 4, bSrc + i * 32 * 256 + koff);
            asm volatile("cp.async.commit_group;" ::: "memory");
        }

        unsigned aob = cur * LA_B, bob = cur * LB_B;
        #pragma unroll
        for (int ks = 0; ks < 4; ks++) {
            unsigned a0[4], a1[4];
            ldsm4(a0, aAddr0 + aob + ks * 32);
            ldsm4(a1, aAddr1 + aob + ks * 32);
            #pragma unroll
            for (int np = 0; np < 4; np++) {
                unsigned bf[4];
                ldsm4(bf, bAddr + bob + np * (16 * SSTR * 4) + ks * 32);
                mma_tf32(acc[0][2 * np    ], a0, bf + 0);
                mma_tf32(acc[0][2 * np + 1], a0, bf + 2);
                mma_tf32(acc[1][2 * np    ], a1, bf + 0);
                mma_tf32(acc[1][2 * np + 1], a1, bf + 2);
            }
        }
    }

    // epilogue pass 1: v = acc + bias + residual; LN stats
    float sr[4] = {0.f, 0.f, 0.f, 0.f}, qr[4] = {0.f, 0.f, 0.f, 0.f};
    #pragma unroll
    for (int i = 0; i < 2; i++) {
        int r0 = aRowBase + wm + i * 16 + g;
        #pragma unroll
        for (int j = 0; j < 8; j++) {
            int col = wn + j * 8 + t * 2;
            float bx = bias[col], by = bias[col + 1];
            float2 x0 = *(const float2*)&x[(size_t)r0 * Cn + col];
            float2 x1 = *(const float2*)&x[(size_t)(r0 + 8) * Cn + col];
            acc[i][j][0] += bx + x0.x; acc[i][j][1] += by + x0.y;
            acc[i][j][2] += bx + x1.x; acc[i][j][3] += by + x1.y;
            sr[i * 2]     += acc[i][j][0] + acc[i][j][1];
            qr[i * 2]     += acc[i][j][0] * acc[i][j][0] + acc[i][j][1] * acc[i][j][1];
            sr[i * 2 + 1] += acc[i][j][2] + acc[i][j][3];
            qr[i * 2 + 1] += acc[i][j][2] * acc[i][j][2] + acc[i][j][3] * acc[i][j][3];
        }
    }
    #pragma unroll
    for (int o = 1; o <= 2; o <<= 1) {
        #pragma unroll
        for (int r = 0; r < 4; r++) {
            sr[r] += __shfl_xor_sync(0xFFFFFFFFu, sr[r], o);
            qr[r] += __shfl_xor_sync(0xFFFFFFFFu, qr[r], o);
        }
    }
    __syncthreads();
    float* redS = (float*)smem;
    float* redQ = redS + 256;
    if (t == 0) {
        #pragma unroll
        for (int i = 0; i < 2; i++) {
            int lr = wm + i * 16 + g;
            redS[lr * 4 + nw] = sr[i * 2];       redQ[lr * 4 + nw] = qr[i * 2];
            redS[(lr + 8) * 4 + nw] = sr[i * 2 + 1]; redQ[(lr + 8) * 4 + nw] = qr[i * 2 + 1];
        }
    }
    __syncthreads();

    float mean[4], rinv[4];
    #pragma unroll
    for (int i = 0; i < 2; i++) {
        #pragma unroll
        for (int hf = 0; hf < 2; hf++) {
            int lr = wm + i * 16 + g + hf * 8;
            float S = redS[lr * 4 + 0] + redS[lr * 4 + 1] + redS[lr * 4 + 2] + redS[lr * 4 + 3];
            float Q = redQ[lr * 4 + 0] + redQ[lr * 4 + 1] + redQ[lr * 4 + 2] + redQ[lr * 4 + 3];
            float m = S * (1.f / Cn);
            mean[i * 2 + hf] = m;
            rinv[i * 2 + hf] = rsqrtf(Q * (1.f / Cn) - m * m + EPSF);
        }
    }

    if (!lnfw) {
        #pragma unroll
        for (int i = 0; i < 2; i++) {
            int r0 = aRowBase + wm + i * 16 + g;
            float m0 = mean[i * 2], r0i = rinv[i * 2];
            float m1 = mean[i * 2 + 1], r1i = rinv[i * 2 + 1];
            #pragma unroll
            for (int j = 0; j < 8; j++) {
                int col = wn + j * 8 + t * 2;
                float w0 = lnw[col], w1 = lnw[col + 1];
                float c0 = lnb[col], c1 = lnb[col + 1];
                float o0 = (acc[i][j][0] - m0) * r0i * w0 + c0;
                float o1 = (acc[i][j][1] - m0) * r0i * w1 + c1;
                float o2 = (acc[i][j][2] - m1) * r1i * w0 + c0;
                float o3 = (acc[i][j][3] - m1) * r1i * w1 + c1;
                *(float2*)&x[(size_t)r0 * Cn + col]       = make_float2(o0, o1);
                *(float2*)&x[(size_t)(r0 + 8) * Cn + col] = make_float2(o2, o3);
                *(uint2*)&xs[(size_t)r0 * Cn + col]       = make_uint2(f2tf(o0), f2tf(o1));
                *(uint2*)&xs[(size_t)(r0 + 8) * Cn + col] = make_uint2(f2tf(o2), f2tf(o3));
            }
        }
    } else {
        // second LN pass (final lnf fused): o = LN2(v); xs = tf32(LNf(o)); no x write
        float sr2[4] = {0.f, 0.f, 0.f, 0.f}, qr2[4] = {0.f, 0.f, 0.f, 0.f};
        #pragma unroll
        for (int i = 0; i < 2; i++) {
            float m0 = mean[i * 2], r0i = rinv[i * 2];
            float m1 = mean[i * 2 + 1], r1i = rinv[i * 2 + 1];
            #pragma unroll
            for (int j = 0; j < 8; j++) {
                int col = wn + j * 8 + t * 2;
                float w0 = lnw[col], w1 = lnw[col + 1];
                float c0 = lnb[col], c1 = lnb[col + 1];
                acc[i][j][0] = (acc[i][j][0] - m0) * r0i * w0 + c0;
                acc[i][j][1] = (acc[i][j][1] - m0) * r0i * w1 + c1;
                acc[i][j][2] = (acc[i][j][2] - m1) * r1i * w0 + c0;
                acc[i][j][3] = (acc[i][j][3] - m1) * r1i * w1 + c1;
                sr2[i * 2]     += acc[i][j][0] + acc[i][j][1];
                qr2[i * 2]     += acc[i][j][0] * acc[i][j][0] + acc[i][j][1] * acc[i][j][1];
                sr2[i * 2 + 1] += acc[i][j][2] + acc[i][j][3];
                qr2[i * 2 + 1] += acc[i][j][2] * acc[i][j][2] + acc[i][j][3] * acc[i][j][3];
            }
        }
        #pragma unroll
        for (int o = 1; o <= 2; o <<= 1) {
            #pragma unroll
            for (int r = 0; r < 4; r++) {
                sr2[r] += __shfl_xor_sync(0xFFFFFFFFu, sr2[r], o);
                qr2[r] += __shfl_xor_sync(0xFFFFFFFFu, qr2[r], o);
            }
        }
        __syncthreads();   // all first-pass reads of redS/redQ done
        if (t == 0) {
            #pragma unroll
            for (int i = 0; i < 2; i++) {
                int lr = wm + i * 16 + g;
                redS[lr * 4 + nw] = sr2[i * 2];       redQ[lr * 4 + nw] = qr2[i * 2];
                redS[(lr + 8) * 4 + nw] = sr2[i * 2 + 1]; redQ[(lr + 8) * 4 + nw] = qr2[i * 2 + 1];
            }
        }
        __syncthreads();
        float mean2[4], rinv2[4];
        #pragma unroll
        for (int i = 0; i < 2; i++) {
            #pragma unroll
            for (int hf = 0; hf < 2; hf++) {
                int lr = wm + i * 16 + g + hf * 8;
                float S = redS[lr * 4 + 0] + redS[lr * 4 + 1] + redS[lr * 4 + 2] + redS[lr * 4 + 3];
                float Q = redQ[lr * 4 + 0] + redQ[lr * 4 + 1] + redQ[lr * 4 + 2] + redQ[lr * 4 + 3];
                float m = S * (1.f / Cn);
                mean2[i * 2 + hf] = m;
                rinv2[i * 2 + hf] = rsqrtf(Q * (1.f / Cn) - m * m + EPSF);
            }
        }
        #pragma unroll
        for (int i = 0; i < 2; i++) {
            int r0 = aRowBase + wm + i * 16 + g;
            float m0 = mean2[i * 2], r0i = rinv2[i * 2];
            float m1 = mean2[i * 2 + 1], r1i = rinv2[i * 2 + 1];
            #pragma unroll
            for (int j = 0; j < 8; j++) {
                int col = wn + j * 8 + t * 2;
                float w0 = lnfw[col], w1 = lnfw[col + 1];
                float c0 = lnfb[col], c1 = lnfb[col + 1];
                float o0 = (acc[i][j][0] - m0) * r0i * w0 + c0;
                float o1 = (acc[i][j][1] - m0) * r0i * w1 + c1;
                float o2 = (acc[i][j][2] - m1) * r1i * w0 + c0;
                float o3 = (acc[i][j][3] - m1) * r1i * w1 + c1;
                *(uint2*)&xs[(size_t)r0 * Cn + col]       = make_uint2(f2tf(o0), f2tf(o1));
                *(uint2*)&xs[(size_t)(r0 + 8) * Cn + col] = make_uint2(f2tf(o2), f2tf(o3));
            }
        }
    }
}

// ---------------- Tensor-core flash attention (single barrier per chunk) ----------------
#define AKSTR 36
#define AVSTR 68
#define APSTR 68
#define KBUF  (64*AKSTR)
#define VBUF  (32*AVSTR)
#define ASMEM ((2*KBUF + 2*VBUF + 4*16*APSTR) * 4)

__global__ __launch_bounds__(128, 4) void attn_tc_kernel(
    const unsigned* __restrict__ Qs, const unsigned* __restrict__ Kg,
    const unsigned* __restrict__ VTg, unsigned* __restrict__ Os)
{
    extern __shared__ unsigned dsm[];
    unsigned* sPw = dsm + 2 * KBUF + 2 * VBUF;

    int qb = 3 - blockIdx.x;
    int h  = blockIdx.y;
    int b  = blockIdx.z;
    int tid = threadIdx.x;
    int warp = tid >> 5, lane = tid & 31;
    int g = lane >> 2, t = lane & 3;
    int hsoff = h * HSn;
    int qrow = qb * 64 + warp * 16;

    unsigned qa[4][4];
    {
        const unsigned* Qb = Qs + (size_t)(b * Tn + qrow) * Cn + hsoff;
        #pragma unroll
        for (int ks = 0; ks < 4; ks++) {
            qa[ks][0] = Qb[(size_t)g       * Cn + ks * 8 + t];
            qa[ks][1] = Qb[(size_t)(g + 8) * Cn + ks * 8 + t];
            qa[ks][2] = Qb[(size_t)g       * Cn + ks * 8 + t + 4];
            qa[ks][3] = Qb[(size_t)(g + 8) * Cn + ks * 8 + t + 4];
        }
    }

    const unsigned sK0 = smem_u32(dsm);
    const unsigned sV0 = sK0 + 2 * KBUF * 4;
    const unsigned sP  = sV0 + 2 * VBUF * 4 + warp * (16 * APSTR * 4);
    unsigned* Pw = sPw + warp * (16 * APSTR);

    const unsigned* kSrc = Kg + (size_t)(b * Tn + (tid >> 3)) * Cn + hsoff + (tid & 7) * 4;
    const unsigned  kDst = sK0 + (tid >> 3) * (AKSTR * 4) + (tid & 7) * 16;
    const unsigned* vSrc = VTg + ((size_t)b * Cn + hsoff + (tid >> 4)) * Tn + (tid & 15) * 4;
    const unsigned  vDst = sV0 + (tid >> 4) * (AVSTR * 4) + (tid & 15) * 16;

    const unsigned kfAddr = sK0 + ((((lane >> 4) << 3) + (lane & 7)) * AKSTR + ((lane >> 3) & 1) * 4) * 4;
    const unsigned vfAddr = sV0 + ((((lane >> 4) << 3) + (lane & 7)) * AVSTR + ((lane >> 3) & 1) * 4) * 4;
    const unsigned pfAddr = sP + ((lane & 15) * APSTR + (lane >> 4) * 4) * 4;

    float oa[4][4] = {};
    float m0 = -1e30f, m1 = -1e30f, l0 = 0.f, l1 = 0.f;

    #pragma unroll
    for (int i = 0; i < 4; i++) cp16(kDst + i * 16 * AKSTR * 4, kSrc + (size_t)i * 16 * Cn);
    #pragma unroll
    for (int i = 0; i < 4; i++) cp16(vDst + i * 8 * AVSTR * 4, vSrc + (size_t)i * 8 * Tn);
    asm volatile("cp.async.commit_group;" ::: "memory");

    for (int kc = 0; kc <= qb; kc++) {
        int cur = kc & 1;
        asm volatile("cp.async.wait_group 0;" ::: "memory");
        __syncthreads();   // chunk data ready AND all warps done with the other buffer

        if (kc < qb) {
            int nxt = 1 - cur;
            int koff = (kc + 1) * 64;
            #pragma unroll
            for (int i = 0; i < 4; i++)
                cp16(kDst + nxt * KBUF * 4 + i * 16 * AKSTR * 4,
                     kSrc + (size_t)(koff + i * 16) * Cn);
            #pragma unroll
            for (int i = 0; i < 4; i++)
                cp16(vDst + nxt * VBUF * 4 + i * 8 * AVSTR * 4,
                     vSrc + koff + (size_t)i * 8 * Tn);
            asm volatile("cp.async.commit_group;" ::: "memory");
        }

        unsigned ko = cur * KBUF * 4, vo = cur * VBUF * 4;

        float sc[8][4];
        #pragma unroll
        for (int nf = 0; nf < 8; nf++)
            #pragma unroll
            for (int j = 0; j < 4; j++) sc[nf][j] = 0.f;
        #pragma unroll
        for (int ks = 0; ks < 4; ks++) {
            #pragma unroll
            for (int np = 0; np < 4; np++) {
                unsigned bf[4];
                ldsm4(bf, kfAddr + ko + np * (16 * AKSTR * 4) + ks * 32);
                mma_tf32(sc[2 * np    ], qa[ks], bf + 0);
                mma_tf32(sc[2 * np + 1], qa[ks], bf + 2);
            }
        }

        if (kc == qb) {
            int r0 = warp * 16 + g;
            #pragma unroll
            for (int nf = 0; nf < 8; nf++) {
                int c0 = nf * 8 + 2 * t;
                if (c0     > r0    ) sc[nf][0] = -1e30f;
                if (c0 + 1 > r0    ) sc[nf][1] = -1e30f;
                if (c0     > r0 + 8) sc[nf][2] = -1e30f;
                if (c0 + 1 > r0 + 8) sc[nf][3] = -1e30f;
            }
        }

        float mx0 = -1e30f, mx1 = -1e30f;
        #pragma unroll
        for (int nf = 0; nf < 8; nf++) {
            mx0 = fmaxf(mx0, fmaxf(sc[nf][0], sc[nf][1]));
            mx1 = fmaxf(mx1, fmaxf(sc[nf][2], sc[nf][3]));
        }
        #pragma unroll
        for (int o = 1; o <= 2; o <<= 1) {
            mx0 = fmaxf(mx0, __shfl_xor_sync(0xFFFFFFFFu, mx0, o));
            mx1 = fmaxf(mx1, __shfl_xor_sync(0xFFFFFFFFu, mx1, o));
        }
        float nm0 = fmaxf(m0, mx0), nm1 = fmaxf(m1, mx1);
        float al0 = __expf(m0 - nm0), al1 = __expf(m1 - nm1);

        float s0 = 0.f, s1 = 0.f;
        #pragma unroll
        for (int nf = 0; nf < 8; nf++) {
            float p0 = __expf(sc[nf][0] - nm0);
            float p1 = __expf(sc[nf][1] - nm0);
            float p2 = __expf(sc[nf][2] - nm1);
            float p3 = __expf(sc[nf][3] - nm1);
            s0 += p0 + p1; s1 += p2 + p3;
            *(uint2*)&Pw[(g    ) * APSTR + nf * 8 + 2 * t] = make_uint2(f2tf(p0), f2tf(p1));
            *(uint2*)&Pw[(g + 8) * APSTR + nf * 8 + 2 * t] = make_uint2(f2tf(p2), f2tf(p3));
        }
        #pragma unroll
        for (int o = 1; o <= 2; o <<= 1) {
            s0 += __shfl_xor_sync(0xFFFFFFFFu, s0, o);
            s1 += __shfl_xor_sync(0xFFFFFFFFu, s1, o);
        }
        l0 = l0 * al0 + s0;
        l1 = l1 * al1 + s1;
        m0 = nm0; m1 = nm1;

        #pragma unroll
        for (int nf = 0; nf < 4; nf++) {
            oa[nf][0] *= al0; oa[nf][1] *= al0;
            oa[nf][2] *= al1; oa[nf][3] *= al1;
        }
        __syncwarp();   // P stores visible to whole warp

        #pragma unroll
        for (int ks = 0; ks < 8; ks++) {
            unsigned pa[4], vb0[4], vb1[4];
            ldsm4(pa,  pfAddr + ks * 32);
            ldsm4(vb0, vfAddr + vo + ks * 32);
            ldsm4(vb1, vfAddr + vo + 16 * AVSTR * 4 + ks * 32);
            mma_tf32(oa[0], pa, vb0 + 0);
            mma_tf32(oa[1], pa, vb0 + 2);
            mma_tf32(oa[2], pa, vb1 + 0);
            mma_tf32(oa[3], pa, vb1 + 2);
        }
        __syncwarp();   // P reads done before next chunk's P stores
    }

    float i0 = 1.f / l0, i1 = 1.f / l1;
    unsigned* Ob = Os + (size_t)(b * Tn + qrow) * Cn + hsoff;
    #pragma unroll
    for (int nf = 0; nf < 4; nf++) {
        int c = nf * 8 + 2 * t;
        *(uint2*)&Ob[(size_t)g       * Cn + c] =
            make_uint2(f2tf(oa[nf][0] * i0), f2tf(oa[nf][1] * i0));
        *(uint2*)&Ob[(size_t)(g + 8) * Cn + c] =
            make_uint2(f2tf(oa[nf][2] * i1), f2tf(oa[nf][3] * i1));
    }
}

// ---------------- Loss ----------------
__global__ __launch_bounds__(256) void loss_row_kernel(
    const float* __restrict__ logits, const int* __restrict__ target,
    float* __restrict__ nll)
{
    int gwarp = (blockIdx.x * blockDim.x + threadIdx.x) >> 5;
    int lane = threadIdx.x & 31;
    if (gwarp >= NROWS) return;
    const float* lg = logits + (size_t)gwarp * Vn;
    float v0 = lg[lane], v1 = lg[lane + 32], v2 = lg[lane + 64];
    float mx = fmaxf(v0, fmaxf(v1, v2));
    #pragma unroll
    for (int o = 16; o; o >>= 1) mx = fmaxf(mx, __shfl_xor_sync(0xFFFFFFFFu, mx, o));
    float s = __expf(v0 - mx) + __expf(v1 - mx) + __expf(v2 - mx);
    #pragma unroll
    for (int o = 16; o; o >>= 1) s += __shfl_xor_sync(0xFFFFFFFFu, s, o);
    if (lane == 0) {
        float lse = mx + logf(s);
        nll[gwarp] = lse - lg[target[gwarp]];
    }
}

__global__ __launch_bounds__(256) void loss_reduce_kernel(
    const float* __restrict__ nll, float* __restrict__ out)
{
    __shared__ float sh[256];
    float s = 0.f;
    for (int i = threadIdx.x; i < NROWS; i += 256) s += nll[i];
    sh[threadIdx.x] = s;
    __syncthreads();
    for (int st = 128; st; st >>= 1) {
        if (threadIdx.x < st) sh[threadIdx.x] += sh[threadIdx.x + st];
        __syncthreads();
    }
    if (threadIdx.x == 0) out[0] = sh[0] * (1.f / NROWS);
}

// ---------------- Host-side launch sequence ----------------
extern "C" void kernel_launch(void* const* d_in, const int* in_sizes, int n_in,
                              void* d_out, int out_size) {
    const int*   idx    = (const int*)  d_in[0];
    const int*   target = (const int*)  d_in[1];
    const float* tok    = (const float*)d_in[2];
    const float* pos    = (const float*)d_in[3];
    const float* Wq     = (const float*)d_in[4];
    const float* Wk     = (const float*)d_in[5];
    const float* Wv     = (const float*)d_in[6];
    const float* Wo     = (const float*)d_in[7];
    const float* bo     = (const float*)d_in[8];
    const float* W1     = (const float*)d_in[9];
    const float* b1     = (const float*)d_in[10];
    const float* W2     = (const float*)d_in[11];
    const float* b2     = (const float*)d_in[12];
    const float* ln1w   = (const float*)d_in[13];
    const float* ln1b   = (const float*)d_in[14];
    const float* ln2w   = (const float*)d_in[15];
    const float* ln2b   = (const float*)d_in[16];
    const float* lnfw   = (const float*)d_in[17];
    const float* lnfb   = (const float*)d_in[18];
    const float* Wlm    = (const float*)d_in[19];
    const float* blm    = (const float*)d_in[20];

    float* logits = (float*)d_out;

    float* s = nullptr;
    cudaGetSymbolAddress((void**)&s, g_scratch);
    unsigned* sh = nullptr;
    cudaGetSymbolAddress((void**)&sh, g_shadow);
    unsigned* wt = nullptr;
    cudaGetSymbolAddress((void**)&wt, g_wt);

    float* x   = s;
    float* nll = s + (size_t)NROWS * Cn;
    unsigned* xs  = sh;
    unsigned* qs  = sh + 1 * (size_t)NROWS * Cn;
    unsigned* ksb = sh + 2 * (size_t)NROWS * Cn;
    unsigned* vts = sh + 3 * (size_t)NROWS * Cn;
    unsigned* bds = sh + 4 * (size_t)NROWS * Cn;
    unsigned* bbs = sh + 5 * (size_t)NROWS * Cn;

    cudaFuncSetAttribute(gemm_tc_kernel,
                         cudaFuncAttributeMaxDynamicSharedMemorySize, GSMEM);
    cudaFuncSetAttribute(gemm_qkv_kernel,
                         cudaFuncAttributeMaxDynamicSharedMemorySize, GSMEM);
    cudaFuncSetAttribute(gemm_ln_kernel,
                         cudaFuncAttributeMaxDynamicSharedMemorySize, LSMEM);
    cudaFuncSetAttribute(attn_tc_kernel,
                         cudaFuncAttributeMaxDynamicSharedMemorySize, ASMEM);

    dim3 gemmGridC(Cn / 64, NROWS / 128);
    dim3 gemmGridV((Vn + 63) / 64, NROWS / 128);
    dim3 qkvGrid(Cn / 64, NROWS / 128, 3);
    dim3 attnGrid(4, Hn, Bn);

    wt_kernel<<<dim3(8, 8, 37), dim3(32, 8)>>>(Wq, Wk, Wv, Wo, W1, W2, Wlm, wt);
    embed_kernel<<<NROWS, 256>>>(idx, tok, pos, x, xs);

    for (int l = 0; l < Ln; l++) {
        const unsigned* wtl = wt + (size_t)l * 6 * CC;
        bool last = (l == Ln - 1);

        gemm_qkv_kernel<<<qkvGrid, 256, GSMEM>>>(xs, wtl, qs, ksb, vts);

        attn_tc_kernel<<<attnGrid, 128, ASMEM>>>(qs, ksb, vts, bds);

        gemm_ln_kernel<<<NROWS / 64, 256, LSMEM>>>(bds, wtl + 3 * CC,
            bo + (size_t)l * Cn, x, xs,
            ln1w + (size_t)l * Cn, ln1b + (size_t)l * Cn, nullptr, nullptr);

        gemm_tc_kernel<<<gemmGridC, 256, GSMEM>>>(xs, wtl + 4 * CC,
            b1 + (size_t)l * Cn, nullptr, bbs, 1.f, Cn, 1);

        gemm_ln_kernel<<<NROWS / 64, 256, LSMEM>>>(bbs, wtl + 5 * CC,
            b2 + (size_t)l * Cn, x, xs,
            ln2w + (size_t)l * Cn, ln2b + (size_t)l * Cn,
            last ? lnfw : nullptr, last ? lnfb : nullptr);
    }

    gemm_tc_kernel<<<gemmGridV, 256, GSMEM>>>(xs, wt + 36 * CC, blm,
        logits, nullptr, 1.f, Vn, 0);

    if (out_size > NROWS * Vn) {
        loss_row_kernel<<<NROWS / 8, 256>>>(logits, target, nll);
        loss_reduce_kernel<<<1, 256>>>(nll, logits + (size_t)NROWS * Vn);
    }
}